// round 3
// baseline (speedup 1.0000x reference)
#include <cuda_runtime.h>
#include <cuda_bf16.h>
#include <cstdint>

// ---------------- problem constants ----------------
#define BATCH   4096
#define NOSC    50
#define NPER    40
#define STEPS   700
#define OBLK    5            // oscillators per k-block
#define NBLK    10           // 50/5
#define KBLK    (OBLK*NPER)  // 200
#define BT      32           // batch tile per CTA
#define NCTA    (BATCH/BT)   // 128
#define APITCH  204          // a-tile row pitch (floats), 16B-aligned rows

#define DTC     0.001f
#define RC      0.02f
#define L0C     0.1f
#define INERT   0.001f
#define DAMPC   0.01f
#define KMUS    50.0f
#define LREST   0.05f
#define TAUM    0.05f
#define HPI     1.5707963267948966f

// ---------------- device scratch (no allocation allowed) ----------------
__device__ float g_os[NOSC * BATCH * 2];     // initial oscillator states [o][b][2]
__device__ float g_direct[BATCH * 2];        // direct term [b][2]
__device__ float g_wt[2000 * 32];            // fc4_w transposed: [k][j]

// ---------------- shared memory layout (bytes) ----------------
// enc   float2[2000]      @ 0        (16000)
// bias  float [2000]      @ 16000    (8000)
// dec   float [4000]      @ 24000    (16000)
// os    float2[50*32]     @ 40000    (12800)
// a     float [32*204]    @ 52800    (26112)
// w     float [200*32]    @ 78912    (25600)
// fc5   float [64]        @ 104512   (256)
#define SM_ENC   0
#define SM_BIAS  16000
#define SM_DEC   24000
#define SM_OS    40000
#define SM_A     52800
#define SM_W     78912
#define SM_FC5   104512
#define SMEM_BYTES 104832

// ============================================================
// Preamble: per-batch MLP -> direct, o0 (g_os), g_direct
// ============================================================
__global__ void pre_kernel(const float* __restrict__ x,
                           const float* __restrict__ fc1_w, const float* __restrict__ fc1_b,
                           const float* __restrict__ fc2_w, const float* __restrict__ fc2_b,
                           const float* __restrict__ fc3_w, const float* __restrict__ fc3_b,
                           const float* __restrict__ fcd_w, const float* __restrict__ fcd_b)
{
    __shared__ float sh[128];
    __shared__ float sh2[128];
    int t = threadIdx.x;
    int b = blockIdx.x;
    float x0 = x[b * 2 + 0];
    float x1 = x[b * 2 + 1];

    float h = fmaf(fc1_w[t * 2 + 0], x0, fmaf(fc1_w[t * 2 + 1], x1, fc1_b[t]));
    h = fmaxf(h, 0.0f);
    sh[t] = h;
    __syncthreads();

    const float4* h4 = (const float4*)sh;

    // h2 = relu(fc2_w @ h + b)
    {
        float acc = fc2_b[t];
        const float4* w4 = (const float4*)&fc2_w[t * 128];
        #pragma unroll 8
        for (int i = 0; i < 32; i++) {
            float4 w = w4[i], hh = h4[i];
            acc = fmaf(w.x, hh.x, acc);
            acc = fmaf(w.y, hh.y, acc);
            acc = fmaf(w.z, hh.z, acc);
            acc = fmaf(w.w, hh.w, acc);
        }
        sh2[t] = fmaxf(acc, 0.0f);
    }

    // direct = fcd_w @ h + fcd_b  (threads 0,1)
    if (t < 2) {
        float acc = fcd_b[t];
        const float4* w4 = (const float4*)&fcd_w[t * 128];
        #pragma unroll 8
        for (int i = 0; i < 32; i++) {
            float4 w = w4[i], hh = h4[i];
            acc = fmaf(w.x, hh.x, acc);
            acc = fmaf(w.y, hh.y, acc);
            acc = fmaf(w.z, hh.z, acc);
            acc = fmaf(w.w, hh.w, acc);
        }
        g_direct[b * 2 + t] = acc;
    }
    __syncthreads();

    // xo = fc3_w @ h2 + fc3_b  -> o0 scattered to [o][b][d]
    if (t < 100) {
        float acc = fc3_b[t];
        const float4* w4 = (const float4*)&fc3_w[t * 128];
        const float4* g4 = (const float4*)sh2;
        #pragma unroll 8
        for (int i = 0; i < 32; i++) {
            float4 w = w4[i], hh = g4[i];
            acc = fmaf(w.x, hh.x, acc);
            acc = fmaf(w.y, hh.y, acc);
            acc = fmaf(w.z, hh.z, acc);
            acc = fmaf(w.w, hh.w, acc);
        }
        int o = t >> 1, d = t & 1;
        g_os[(o * BATCH + b) * 2 + d] = acc;
    }
}

// ============================================================
// Transpose fc4_w (32x2000 row-major) -> g_wt[k][j]
// ============================================================
__global__ void tr_kernel(const float* __restrict__ fc4_w)
{
    int idx = blockIdx.x * 256 + threadIdx.x;
    if (idx < 2000 * 32) {
        int k = idx >> 5;
        int j = idx & 31;
        g_wt[idx] = fc4_w[j * 2000 + k];
    }
}

// ============================================================
// Main persistent simulation kernel: 128 CTAs x 256 thr, BT=32
// ============================================================
extern "C" __global__ void __launch_bounds__(256, 1)
sim_kernel(const float* __restrict__ x,
           const float* __restrict__ enc,
           const float* __restrict__ osc_bias,
           const float* __restrict__ dec,
           const float* __restrict__ fc4_b,
           const float* __restrict__ fc5_w,
           const float* __restrict__ fc5_b,
           float* __restrict__ out_l,     // [STEPS][B][4]
           float* __restrict__ out_act)   // [STEPS][B][2]
{
    extern __shared__ char smem[];
    float2* s_enc  = (float2*)(smem + SM_ENC);    // [o*40+p]
    float*  s_bias = (float*) (smem + SM_BIAS);   // [o*40+p]
    float*  s_dec  = (float*) (smem + SM_DEC);    // [(o*2+d)*40+p]
    float2* s_os   = (float2*)(smem + SM_OS);     // [o*32+bt]
    float*  s_a    = (float*) (smem + SM_A);      // [bt*APITCH + kk]
    float*  s_w    = (float*) (smem + SM_W);      // [kk*32 + j]
    float*  s_fc5  = (float*) (smem + SM_FC5);    // [d*32+j]

    const int tid  = threadIdx.x;
    const int lane = tid & 31;
    const int wrp  = tid >> 5;
    const int j    = lane;
    const int b0   = blockIdx.x * BT;
    const int rb   = wrp * 4;   // batch rows rb..rb+3 of tile handled by this warp

    // ---- load constants into SMEM ----
    for (int i = tid; i < NOSC * NPER; i += 256) s_enc[i]  = ((const float2*)enc)[i];
    for (int i = tid; i < NOSC * NPER; i += 256) s_bias[i] = osc_bias[i];
    for (int i = tid; i < NOSC * 2 * NPER; i += 256) s_dec[i] = dec[i];
    if (tid < 64) s_fc5[tid] = fc5_w[tid];
    for (int i = tid; i < NOSC * BT; i += 256) {
        int o = i / BT, bt = i % BT;
        s_os[o * BT + bt] = ((const float2*)g_os)[o * BATCH + b0 + bt];
    }

    const float fc4b  = fc4_b[j];
    const float fc5b0 = fc5_b[0];
    const float fc5b1 = fc5_b[1];

    // lane 0 of each warp owns limb state + direct for its 4 batch elems
    float th[4], om[4], l1s[4], l2s[4], dir0[4], dir1[4];
    if (lane == 0) {
        #pragma unroll
        for (int i = 0; i < 4; i++) {
            int b = b0 + rb + i;
            float theta = x[b * 2];
            th[i]  = theta;
            om[i]  = 0.0f;
            l1s[i] = L0C - RC * theta;
            l2s[i] = L0C + RC * theta;
            dir0[i] = g_direct[b * 2 + 0];
            dir1[i] = g_direct[b * 2 + 1];
        }
    }
    __syncthreads();

    for (int t = 0; t < STEPS; t++) {
        float acc0 = 0.f, acc1 = 0.f, acc2 = 0.f, acc3 = 0.f;

        for (int ob = 0; ob < NBLK; ob++) {
            // ---- stage fc4 weight panel (k-major) into SMEM ----
            const float* gw = g_wt + ob * (KBLK * 32);
            #pragma unroll
            for (int i = tid; i < KBLK * 32; i += 256) s_w[i] = gw[i];

            // ---- compute a for OBLK oscillators of this block ----
            const int obase = ob * OBLK;
            #pragma unroll
            for (int oi = 0; oi < OBLK; oi++) {
                const int o = obase + oi;
                for (int idx = tid; idx < BT * NPER; idx += 256) {
                    int bb = idx / NPER;
                    int p  = idx - bb * NPER;
                    float2 e  = s_enc[o * NPER + p];
                    float2 os = s_os[o * BT + bb];
                    float v = fmaf(e.x, os.x, fmaf(e.y, os.y, s_bias[o * NPER + p]));
                    s_a[bb * APITCH + oi * NPER + p] = fmaxf(v, 0.0f);
                }
            }
            __syncthreads();

            // ---- fc4 GEMM accumulate: b1[b][j] += a[b][k] * Wt[k][j] ----
            const float* a0p = &s_a[(rb + 0) * APITCH];
            const float* a1p = &s_a[(rb + 1) * APITCH];
            const float* a2p = &s_a[(rb + 2) * APITCH];
            const float* a3p = &s_a[(rb + 3) * APITCH];
            #pragma unroll 2
            for (int kk = 0; kk < KBLK; kk += 4) {
                float w0 = s_w[(kk + 0) * 32 + j];
                float w1 = s_w[(kk + 1) * 32 + j];
                float w2 = s_w[(kk + 2) * 32 + j];
                float w3 = s_w[(kk + 3) * 32 + j];
                float4 a0 = *(const float4*)(a0p + kk);
                float4 a1 = *(const float4*)(a1p + kk);
                float4 a2 = *(const float4*)(a2p + kk);
                float4 a3 = *(const float4*)(a3p + kk);
                acc0 = fmaf(a0.x, w0, acc0); acc0 = fmaf(a0.y, w1, acc0);
                acc0 = fmaf(a0.z, w2, acc0); acc0 = fmaf(a0.w, w3, acc0);
                acc1 = fmaf(a1.x, w0, acc1); acc1 = fmaf(a1.y, w1, acc1);
                acc1 = fmaf(a1.z, w2, acc1); acc1 = fmaf(a1.w, w3, acc1);
                acc2 = fmaf(a2.x, w0, acc2); acc2 = fmaf(a2.y, w1, acc2);
                acc2 = fmaf(a2.z, w2, acc2); acc2 = fmaf(a2.w, w3, acc2);
                acc3 = fmaf(a3.x, w0, acc3); acc3 = fmaf(a3.y, w1, acc3);
                acc3 = fmaf(a3.z, w2, acc3); acc3 = fmaf(a3.w, w3, acc3);
            }

            // ---- deriv = dec . a ; os += DT*deriv  (for this block's oscillators) ----
            for (int task = tid; task < OBLK * BT * 2; task += 256) {
                int oi = task / (BT * 2);
                int r  = task - oi * (BT * 2);
                int bb = r >> 1;
                int d  = r & 1;
                int o  = obase + oi;
                const float* dp = &s_dec[(o * 2 + d) * NPER];
                const float* ap = &s_a[bb * APITCH + oi * NPER];
                float s = 0.0f;
                #pragma unroll
                for (int p = 0; p < NPER; p++) s = fmaf(dp[p], ap[p], s);
                if (d == 0) s_os[o * BT + bb].x += DTC * s;
                else        s_os[o * BT + bb].y += DTC * s;
            }
            __syncthreads();
        }

        // ---- b1 = relu(acc + fc4_b); activation = fc5 @ b1 + fc5_b + direct ----
        float b1v[4];
        b1v[0] = fmaxf(acc0 + fc4b, 0.0f);
        b1v[1] = fmaxf(acc1 + fc4b, 0.0f);
        b1v[2] = fmaxf(acc2 + fc4b, 0.0f);
        b1v[3] = fmaxf(acc3 + fc4b, 0.0f);
        float w5a = s_fc5[lane];        // fc5_w[0][j]
        float w5b = s_fc5[32 + lane];   // fc5_w[1][j]

        #pragma unroll
        for (int i = 0; i < 4; i++) {
            float v0 = w5a * b1v[i];
            float v1 = w5b * b1v[i];
            #pragma unroll
            for (int off = 16; off > 0; off >>= 1) {
                v0 += __shfl_xor_sync(0xffffffffu, v0, off);
                v1 += __shfl_xor_sync(0xffffffffu, v1, off);
            }
            if (lane == 0) {
                float A0 = v0 + fc5b0 + dir0[i];
                float A1 = v1 + fc5b1 + dir1[i];
                // limb dynamics (fp32, matches reference ordering)
                float f1 = fmaxf(A0, 0.0f) * KMUS * fmaxf(l1s[i] - LREST, 0.0f);
                float f2 = fmaxf(A1, 0.0f) * KMUS * fmaxf(l2s[i] - LREST, 0.0f);
                float domega = (RC * (f2 - f1) - DAMPC * om[i]) / INERT;
                float dl1 = ((L0C - RC * th[i]) - l1s[i]) / TAUM;
                float dl2 = ((L0C + RC * th[i]) - l2s[i]) / TAUM;
                float pos = th[i] + DTC * om[i];
                float vel = om[i] + DTC * domega;
                float nl1 = l1s[i] + DTC * dl1;
                float nl2 = l2s[i] + DTC * dl2;
                bool inb = (pos > -HPI) && (pos < HPI);
                float cpos = fminf(fmaxf(pos, -HPI), HPI);
                float cvel = inb ? vel : 0.0f;
                th[i] = cpos; om[i] = cvel; l1s[i] = nl1; l2s[i] = nl2;
                int b = b0 + rb + i;
                size_t lidx = ((size_t)t * BATCH + b);
                *(float4*)&out_l[lidx * 4]   = make_float4(cpos, cvel, nl1, nl2);
                *(float2*)&out_act[lidx * 2] = make_float2(A0, A1);
            }
        }
    }
}

// ============================================================
// Launch
// ============================================================
extern "C" void kernel_launch(void* const* d_in, const int* in_sizes, int n_in,
                              void* d_out, int out_size)
{
    const float* x      = (const float*)d_in[0];
    const float* fc1_w  = (const float*)d_in[1];
    const float* fc1_b  = (const float*)d_in[2];
    const float* fc2_w  = (const float*)d_in[3];
    const float* fc2_b  = (const float*)d_in[4];
    const float* fc3_w  = (const float*)d_in[5];
    const float* fc3_b  = (const float*)d_in[6];
    const float* fcd_w  = (const float*)d_in[7];
    const float* fcd_b  = (const float*)d_in[8];
    const float* enc    = (const float*)d_in[9];
    const float* oscb   = (const float*)d_in[10];
    const float* dec    = (const float*)d_in[11];
    const float* fc4_w  = (const float*)d_in[12];
    const float* fc4_b  = (const float*)d_in[13];
    const float* fc5_w  = (const float*)d_in[14];
    const float* fc5_b  = (const float*)d_in[15];

    float* out   = (float*)d_out;
    float* out_l = out;                                   // STEPS*B*4
    float* out_a = out + (size_t)STEPS * BATCH * 4;       // STEPS*B*2

    cudaFuncSetAttribute(sim_kernel, cudaFuncAttributeMaxDynamicSharedMemorySize, SMEM_BYTES);

    pre_kernel<<<BATCH, 128>>>(x, fc1_w, fc1_b, fc2_w, fc2_b, fc3_w, fc3_b, fcd_w, fcd_b);
    tr_kernel<<<(2000 * 32 + 255) / 256, 256>>>(fc4_w);
    sim_kernel<<<NCTA, 256, SMEM_BYTES>>>(x, enc, oscb, dec, fc4_b, fc5_w, fc5_b, out_l, out_a);
}

// round 5
// speedup vs baseline: 1.6823x; 1.6823x over previous
#include <cuda_runtime.h>
#include <cuda_bf16.h>
#include <cstdint>

// ---------------- problem constants ----------------
#define BATCH   4096
#define NOSC    50
#define NPER    40
#define STEPS   700
#define BT      32
#define NCTA    (BATCH/BT)   // 128

#define DTC     0.001f
#define RC      0.02f
#define L0C     0.1f
#define INERT   0.001f
#define DAMPC   0.01f
#define KMUS    50.0f
#define LREST   0.05f
#define TAUM    0.05f
#define HPI     1.5707963267948966f

// W fragment store: [ob(10)][kstep(13)][ntile(4)][lane(32)][reg(2)] u32 (bf16x2)
#define WF_U32  (10*13*4*32*2)   // 33280

// ---------------- device scratch ----------------
__device__ float    g_os[NOSC * BATCH * 2];   // initial oscillator states [o][b][2]
__device__ float    g_direct[BATCH * 2];      // direct term [b][2]
__device__ uint32_t g_wfrag[WF_U32];          // fc4_w in MMA B-fragment layout (bf16x2)

// ---------------- shared memory layout (bytes, all 16B aligned) ----------------
#define SM_WF    0         // 133120  : all W fragments (10 blocks)
#define SM_AF    133120    // 13312   : A fragments for one block [ks(13)][mt(2)][lane(32)][reg(4)] u32
#define SM_ENC   146432    // 16800   : enc float2, row pitch 42
#define SM_BIAS  163232    // 8400    : bias float,  row pitch 42
#define SM_DEC   171632    // 16800   : dec float,   row pitch 42 per (o,d)
#define SM_OS    188432    // 13200   : osc states float2, pitch 33
#define SM_PART  201632    // 1024    : fc5 partials [m(32)][d(2)][ntile(4)]
#define SMEM_BYTES 202656

#define ESTR  42
#define OSSTR 33

// ============================================================
// Preamble: per-batch MLP -> direct, o0 (g_os), g_direct
// ============================================================
__global__ void pre_kernel(const float* __restrict__ x,
                           const float* __restrict__ fc1_w, const float* __restrict__ fc1_b,
                           const float* __restrict__ fc2_w, const float* __restrict__ fc2_b,
                           const float* __restrict__ fc3_w, const float* __restrict__ fc3_b,
                           const float* __restrict__ fcd_w, const float* __restrict__ fcd_b)
{
    __shared__ float sh[128];
    __shared__ float sh2[128];
    int t = threadIdx.x;
    int b = blockIdx.x;
    float x0 = x[b * 2 + 0];
    float x1 = x[b * 2 + 1];

    float h = fmaf(fc1_w[t * 2 + 0], x0, fmaf(fc1_w[t * 2 + 1], x1, fc1_b[t]));
    h = fmaxf(h, 0.0f);
    sh[t] = h;
    __syncthreads();

    const float4* h4 = (const float4*)sh;

    {
        float acc = fc2_b[t];
        const float4* w4 = (const float4*)&fc2_w[t * 128];
        #pragma unroll 8
        for (int i = 0; i < 32; i++) {
            float4 w = w4[i], hh = h4[i];
            acc = fmaf(w.x, hh.x, acc);
            acc = fmaf(w.y, hh.y, acc);
            acc = fmaf(w.z, hh.z, acc);
            acc = fmaf(w.w, hh.w, acc);
        }
        sh2[t] = fmaxf(acc, 0.0f);
    }

    if (t < 2) {
        float acc = fcd_b[t];
        const float4* w4 = (const float4*)&fcd_w[t * 128];
        #pragma unroll 8
        for (int i = 0; i < 32; i++) {
            float4 w = w4[i], hh = h4[i];
            acc = fmaf(w.x, hh.x, acc);
            acc = fmaf(w.y, hh.y, acc);
            acc = fmaf(w.z, hh.z, acc);
            acc = fmaf(w.w, hh.w, acc);
        }
        g_direct[b * 2 + t] = acc;
    }
    __syncthreads();

    if (t < 100) {
        float acc = fc3_b[t];
        const float4* w4 = (const float4*)&fc3_w[t * 128];
        const float4* g4 = (const float4*)sh2;
        #pragma unroll 8
        for (int i = 0; i < 32; i++) {
            float4 w = w4[i], hh = g4[i];
            acc = fmaf(w.x, hh.x, acc);
            acc = fmaf(w.y, hh.y, acc);
            acc = fmaf(w.z, hh.z, acc);
            acc = fmaf(w.w, hh.w, acc);
        }
        int o = t >> 1, d = t & 1;
        g_os[(o * BATCH + b) * 2 + d] = acc;
    }
}

// ============================================================
// Build fc4_w B-fragments (bf16x2), zero-padded k 200..207 per block
// idx = (((ob*13 + kstep)*4 + ntile)*32 + lane)*2 + reg
// element mapping (m16n8k16 col B): n = lane>>2, kk0 = reg*8 + (lane&3)*2
// ============================================================
__global__ void wf_kernel(const float* __restrict__ fc4_w)
{
    int idx = blockIdx.x * 256 + threadIdx.x;
    if (idx >= WF_U32) return;
    int reg   = idx & 1;
    int lane  = (idx >> 1) & 31;
    int ntile = (idx >> 6) & 3;
    int rest  = idx >> 8;          // ob*13 + kstep
    int kstep = rest % 13;
    int ob    = rest / 13;
    int kk0 = reg * 8 + (lane & 3) * 2;
    int n   = lane >> 2;
    int kl  = kstep * 16 + kk0;
    int j   = ntile * 8 + n;
    int kg  = ob * 200 + kl;
    float v0 = (kl     < 200) ? fc4_w[j * 2000 + kg]     : 0.0f;
    float v1 = (kl + 1 < 200) ? fc4_w[j * 2000 + kg + 1] : 0.0f;
    uint32_t pk;
    asm("cvt.rn.bf16x2.f32 %0, %1, %2;" : "=r"(pk) : "f"(v1), "f"(v0)); // lo=v0(k), hi=v1(k+1)
    g_wfrag[idx] = pk;
}

// ============================================================
// Main persistent simulation kernel: 128 CTAs x 256 thr, BT=32
// ============================================================
#define MMA_STEP(C, KS) do {                                                   \
    uint4 Af = *(const uint4*)(afp + (KS) * 256);                              \
    uint2 Bf = *(const uint2*)(wfp + (KS) * 256);                              \
    asm volatile(                                                              \
        "mma.sync.aligned.m16n8k16.row.col.f32.bf16.bf16.f32 "                 \
        "{%0,%1,%2,%3}, {%4,%5,%6,%7}, {%8,%9}, {%0,%1,%2,%3};\n"              \
        : "+f"(C.x), "+f"(C.y), "+f"(C.z), "+f"(C.w)                           \
        : "r"(Af.x), "r"(Af.y), "r"(Af.z), "r"(Af.w), "r"(Bf.x), "r"(Bf.y));   \
} while (0)

extern "C" __global__ void __launch_bounds__(256, 1)
sim_kernel(const float* __restrict__ x,
           const float* __restrict__ enc,
           const float* __restrict__ osc_bias,
           const float* __restrict__ dec,
           const float* __restrict__ fc4_b,
           const float* __restrict__ fc5_w,
           const float* __restrict__ fc5_b,
           float* __restrict__ out_l,     // [STEPS][B][4]
           float* __restrict__ out_act)   // [STEPS][B][2]
{
    extern __shared__ char smem[];
    uint32_t* s_wf   = (uint32_t*)(smem + SM_WF);
    uint32_t* s_af   = (uint32_t*)(smem + SM_AF);
    float2*   s_enc  = (float2*)  (smem + SM_ENC);
    float*    s_bias = (float*)   (smem + SM_BIAS);
    float*    s_dec  = (float*)   (smem + SM_DEC);
    float2*   s_os   = (float2*)  (smem + SM_OS);
    float*    s_part = (float*)   (smem + SM_PART);

    const int tid  = threadIdx.x;
    const int lane = tid & 31;
    const int wrp  = tid >> 5;
    const int b0   = blockIdx.x * BT;

    // ---- init: zero A-fragment buffer (padding slots must stay 0) ----
    for (int i = tid; i < 3328; i += 256) s_af[i] = 0u;
    // ---- load all W fragments once ----
    {
        const uint4* src = (const uint4*)g_wfrag;
        uint4* dst = (uint4*)s_wf;
        for (int i = tid; i < WF_U32 / 4; i += 256) dst[i] = src[i];
    }
    // ---- enc/bias (padded pitch 42) ----
    for (int i = tid; i < NOSC * NPER; i += 256) {
        int o = i / NPER, p = i - o * NPER;
        s_enc [o * ESTR + p] = ((const float2*)enc)[i];
        s_bias[o * ESTR + p] = osc_bias[i];
    }
    for (int i = tid; i < NOSC * 2 * NPER; i += 256) {
        int r = i / NPER, p = i - r * NPER;
        s_dec[r * ESTR + p] = dec[i];
    }
    for (int i = tid; i < NOSC * BT; i += 256) {
        int o = i >> 5, b = i & 31;
        s_os[o * OSSTR + b] = ((const float2*)g_os)[o * BATCH + b0 + b];
    }

    // ---- epilogue per-thread constants (warp tile: mtile 0..1, ntile 0..3) ----
    const int mtile = wrp >> 2;
    const int ntile = wrp & 3;
    const int j0 = ntile * 8 + ((lane & 3) << 1);
    const float b4j0  = fc4_b[j0],      b4j1  = fc4_b[j0 + 1];
    const float w50j0 = fc5_w[j0],      w50j1 = fc5_w[j0 + 1];
    const float w51j0 = fc5_w[32 + j0], w51j1 = fc5_w[32 + j0 + 1];

    // ---- warp0 limb state: one batch element per lane ----
    float th = 0.f, om = 0.f, l1s = 0.f, l2s = 0.f, dir0 = 0.f, dir1 = 0.f;
    float fc5b0 = 0.f, fc5b1 = 0.f;
    if (wrp == 0) {
        int b = b0 + lane;
        th  = x[b * 2];
        om  = 0.f;
        l1s = L0C - RC * th;
        l2s = L0C + RC * th;
        dir0 = g_direct[b * 2 + 0];
        dir1 = g_direct[b * 2 + 1];
        fc5b0 = fc5_b[0];
        fc5b1 = fc5_b[1];
    }

    // ---- fused-phase task constants: 160 tasks = (b 0..31) x (oi 0..4),
    //      task = wrp*20 + lane, lanes 20..31 idle ----
    const bool actv = (lane < 20);
    const int  task = wrp * 20 + lane;
    const int  tb   = task / 5;           // batch row 0..31
    const int  toi  = task - tb * 5;      // oscillator within block 0..4
    const int  tmt  = tb >> 4;            // mtile for frag store
    const int  tbb7 = tb & 7;
    const int  tregm = (tb >> 3) & 1;

    // MMA load base pointers
    const uint32_t* afp = s_af + (mtile * 32 + lane) * 4;

    __syncthreads();

    for (int t = 0; t < STEPS; t++) {
        float4 acc0 = make_float4(0.f, 0.f, 0.f, 0.f);
        float4 acc1 = make_float4(0.f, 0.f, 0.f, 0.f);
        float4 acc2 = make_float4(0.f, 0.f, 0.f, 0.f);
        float4 acc3 = make_float4(0.f, 0.f, 0.f, 0.f);

        #pragma unroll 1
        for (int ob = 0; ob < 10; ob++) {
            // ===== fused phase: a (bf16 frag) + deriv + oscillator update =====
            if (actv) {
                const int o = ob * 5 + toi;
                float2 osv = s_os[o * OSSTR + tb];
                float s0 = 0.f, s1 = 0.f;
                const float4* ep  = (const float4*)(s_enc + o * ESTR);
                const float2* bp  = (const float2*)(s_bias + o * ESTR);
                const float2* d0p = (const float2*)(s_dec + (o * 2) * ESTR);
                const float2* d1p = (const float2*)(s_dec + (o * 2 + 1) * ESTR);
                const int klb = toi * 40;
                #pragma unroll 4
                for (int pp = 0; pp < 20; pp++) {
                    float4 e  = ep[pp];
                    float2 bi = bp[pp];
                    float a0 = fmaxf(fmaf(e.x, osv.x, fmaf(e.y, osv.y, bi.x)), 0.f);
                    float a1 = fmaxf(fmaf(e.z, osv.x, fmaf(e.w, osv.y, bi.y)), 0.f);
                    float2 dv0 = d0p[pp];
                    float2 dv1 = d1p[pp];
                    s0 = fmaf(dv0.x, a0, fmaf(dv0.y, a1, s0));
                    s1 = fmaf(dv1.x, a0, fmaf(dv1.y, a1, s1));
                    uint32_t pk;
                    asm("cvt.rn.bf16x2.f32 %0, %1, %2;" : "=r"(pk) : "f"(a1), "f"(a0));
                    int kl = klb + pp * 2;
                    int ks = kl >> 4;
                    int kk = kl & 15;
                    int lidx = (tbb7 << 2) | ((kk & 7) >> 1);
                    int reg  = ((kk >> 3) << 1) | tregm;
                    s_af[(((ks << 1) + tmt) << 7) + (lidx << 2) + reg] = pk;
                }
                s_os[o * OSSTR + tb] = make_float2(osv.x + DTC * s0, osv.y + DTC * s1);
            }
            __syncthreads();

            // ===== MMA: C[32x32] += A[32x208] * W[208x32] (bf16, f32 acc) =====
            {
                const uint32_t* wfp = s_wf + ob * 3328 + (ntile * 32 + lane) * 2;
                MMA_STEP(acc0, 0);  MMA_STEP(acc1, 1);  MMA_STEP(acc2, 2);  MMA_STEP(acc3, 3);
                MMA_STEP(acc0, 4);  MMA_STEP(acc1, 5);  MMA_STEP(acc2, 6);  MMA_STEP(acc3, 7);
                MMA_STEP(acc0, 8);  MMA_STEP(acc1, 9);  MMA_STEP(acc2, 10); MMA_STEP(acc3, 11);
                MMA_STEP(acc0, 12);
            }
            __syncthreads();
        }

        // ===== epilogue: b1 = relu(C + fc4_b); fc5 partials; limb =====
        float c0 = (acc0.x + acc1.x) + (acc2.x + acc3.x);
        float c1 = (acc0.y + acc1.y) + (acc2.y + acc3.y);
        float c2 = (acc0.z + acc1.z) + (acc2.z + acc3.z);
        float c3 = (acc0.w + acc1.w) + (acc2.w + acc3.w);
        float b00 = fmaxf(c0 + b4j0, 0.f);   // row r,   col j0
        float b01 = fmaxf(c1 + b4j1, 0.f);   // row r,   col j1
        float b10 = fmaxf(c2 + b4j0, 0.f);   // row r+8, col j0
        float b11 = fmaxf(c3 + b4j1, 0.f);   // row r+8, col j1
        float p00 = fmaf(w50j0, b00, w50j1 * b01);
        float p01 = fmaf(w51j0, b00, w51j1 * b01);
        float p10 = fmaf(w50j0, b10, w50j1 * b11);
        float p11 = fmaf(w51j0, b10, w51j1 * b11);
        #pragma unroll
        for (int off = 1; off <= 2; off <<= 1) {
            p00 += __shfl_xor_sync(0xffffffffu, p00, off);
            p01 += __shfl_xor_sync(0xffffffffu, p01, off);
            p10 += __shfl_xor_sync(0xffffffffu, p10, off);
            p11 += __shfl_xor_sync(0xffffffffu, p11, off);
        }
        if ((lane & 3) == 0) {
            int m0 = mtile * 16 + (lane >> 2);
            s_part[m0 * 8 + ntile]           = p00;
            s_part[m0 * 8 + 4 + ntile]       = p01;
            s_part[(m0 + 8) * 8 + ntile]     = p10;
            s_part[(m0 + 8) * 8 + 4 + ntile] = p11;
        }
        __syncthreads();

        if (wrp == 0) {
            float4 q0 = *(const float4*)(s_part + lane * 8);
            float4 q1 = *(const float4*)(s_part + lane * 8 + 4);
            float A0 = fc5b0 + dir0 + ((q0.x + q0.y) + (q0.z + q0.w));
            float A1 = fc5b1 + dir1 + ((q1.x + q1.y) + (q1.z + q1.w));
            float f1 = fmaxf(A0, 0.f) * KMUS * fmaxf(l1s - LREST, 0.f);
            float f2 = fmaxf(A1, 0.f) * KMUS * fmaxf(l2s - LREST, 0.f);
            float domega = (RC * (f2 - f1) - DAMPC * om) / INERT;
            float dl1 = ((L0C - RC * th) - l1s) / TAUM;
            float dl2 = ((L0C + RC * th) - l2s) / TAUM;
            float pos = th + DTC * om;
            float vel = om + DTC * domega;
            l1s += DTC * dl1;
            l2s += DTC * dl2;
            bool inb = (pos > -HPI) && (pos < HPI);
            th = fminf(fmaxf(pos, -HPI), HPI);
            om = inb ? vel : 0.f;
            size_t lidx = (size_t)t * BATCH + b0 + lane;
            *(float4*)(out_l + lidx * 4)   = make_float4(th, om, l1s, l2s);
            *(float2*)(out_act + lidx * 2) = make_float2(A0, A1);
        }
    }
}

// ============================================================
// Launch
// ============================================================
extern "C" void kernel_launch(void* const* d_in, const int* in_sizes, int n_in,
                              void* d_out, int out_size)
{
    const float* x      = (const float*)d_in[0];
    const float* fc1_w  = (const float*)d_in[1];
    const float* fc1_b  = (const float*)d_in[2];
    const float* fc2_w  = (const float*)d_in[3];
    const float* fc2_b  = (const float*)d_in[4];
    const float* fc3_w  = (const float*)d_in[5];
    const float* fc3_b  = (const float*)d_in[6];
    const float* fcd_w  = (const float*)d_in[7];
    const float* fcd_b  = (const float*)d_in[8];
    const float* enc    = (const float*)d_in[9];
    const float* oscb   = (const float*)d_in[10];
    const float* dec    = (const float*)d_in[11];
    const float* fc4_w  = (const float*)d_in[12];
    const float* fc4_b  = (const float*)d_in[13];
    const float* fc5_w  = (const float*)d_in[14];
    const float* fc5_b  = (const float*)d_in[15];

    float* out   = (float*)d_out;
    float* out_l = out;                                   // STEPS*B*4
    float* out_a = out + (size_t)STEPS * BATCH * 4;       // STEPS*B*2

    cudaFuncSetAttribute(sim_kernel, cudaFuncAttributeMaxDynamicSharedMemorySize, SMEM_BYTES);

    pre_kernel<<<BATCH, 128>>>(x, fc1_w, fc1_b, fc2_w, fc2_b, fc3_w, fc3_b, fcd_w, fcd_b);
    wf_kernel<<<(WF_U32 + 255) / 256, 256>>>(fc4_w);
    sim_kernel<<<NCTA, 256, SMEM_BYTES>>>(x, enc, oscb, dec, fc4_b, fc5_w, fc5_b, out_l, out_a);
}

// round 6
// speedup vs baseline: 4.9761x; 2.9579x over previous
#include <cuda_runtime.h>
#include <cuda_bf16.h>
#include <cstdint>

// ---------------- problem constants ----------------
#define BATCH   4096
#define NOSC    50
#define NPER    40
#define STEPS   700
#define BT      32
#define NCTA    (BATCH/BT)   // 128
#define NTHR    512

#define DTC     0.001f
#define RC      0.02f
#define L0C     0.1f
#define INERT   0.001f
#define DAMPC   0.01f
#define KMUS    50.0f
#define LREST   0.05f
#define TAUM    0.05f
#define HPI     1.5707963267948966f

#define NKS     125                  // 2000 / 16 k-steps
// W fragment store: [ks(125)][ntile(4)][lane(32)][reg(2)] u32 (bf16x2)
#define WF_U32  (NKS*4*32*2)         // 32000

// ---------------- device scratch ----------------
__device__ float    g_os[NOSC * BATCH * 2];   // initial oscillator states [o][b][2]
__device__ float    g_direct[BATCH * 2];      // direct term [b][2]
__device__ uint32_t g_wfrag[WF_U32];          // fc4_w in MMA B-fragment layout

// ---------------- shared memory layout (bytes, all 16B aligned) ----------------
// A-frag: [ks(125)][mt(2)][128 u32 chunk] ; chunk word = (tbb7<<4)|((c<<2)^mx)|r
#define SM_AF    0         // 128000
#define SM_ENC   128000    // 16800 : enc float2, row pitch 42
#define SM_BIAS  144800    // 8400  : bias float, row pitch 42
#define SM_DEC   153200    // 16800 : dec float, row pitch 42 per (o,d)
#define SM_OS    170000    // 13200 : osc states float2, pitch 33
#define SM_CH    183200    // 4096  : k-half-1 C partials [mt*4+nt][lane] float4
#define SM_PART  187296    // 1024  : fc5 partials [m(32)][d(2)][nt(4)]
#define SMEM_BYTES 188320

#define ESTR  42
#define OSSTR 33

// ============================================================
// Preamble: per-batch MLP -> direct, o0 (g_os), g_direct
// ============================================================
__global__ void pre_kernel(const float* __restrict__ x,
                           const float* __restrict__ fc1_w, const float* __restrict__ fc1_b,
                           const float* __restrict__ fc2_w, const float* __restrict__ fc2_b,
                           const float* __restrict__ fc3_w, const float* __restrict__ fc3_b,
                           const float* __restrict__ fcd_w, const float* __restrict__ fcd_b)
{
    __shared__ float sh[128];
    __shared__ float sh2[128];
    int t = threadIdx.x;
    int b = blockIdx.x;
    float x0 = x[b * 2 + 0];
    float x1 = x[b * 2 + 1];

    float h = fmaf(fc1_w[t * 2 + 0], x0, fmaf(fc1_w[t * 2 + 1], x1, fc1_b[t]));
    h = fmaxf(h, 0.0f);
    sh[t] = h;
    __syncthreads();

    const float4* h4 = (const float4*)sh;

    {
        float acc = fc2_b[t];
        const float4* w4 = (const float4*)&fc2_w[t * 128];
        #pragma unroll 8
        for (int i = 0; i < 32; i++) {
            float4 w = w4[i], hh = h4[i];
            acc = fmaf(w.x, hh.x, acc);
            acc = fmaf(w.y, hh.y, acc);
            acc = fmaf(w.z, hh.z, acc);
            acc = fmaf(w.w, hh.w, acc);
        }
        sh2[t] = fmaxf(acc, 0.0f);
    }

    if (t < 2) {
        float acc = fcd_b[t];
        const float4* w4 = (const float4*)&fcd_w[t * 128];
        #pragma unroll 8
        for (int i = 0; i < 32; i++) {
            float4 w = w4[i], hh = h4[i];
            acc = fmaf(w.x, hh.x, acc);
            acc = fmaf(w.y, hh.y, acc);
            acc = fmaf(w.z, hh.z, acc);
            acc = fmaf(w.w, hh.w, acc);
        }
        g_direct[b * 2 + t] = acc;
    }
    __syncthreads();

    if (t < 100) {
        float acc = fc3_b[t];
        const float4* w4 = (const float4*)&fc3_w[t * 128];
        const float4* g4 = (const float4*)sh2;
        #pragma unroll 8
        for (int i = 0; i < 32; i++) {
            float4 w = w4[i], hh = g4[i];
            acc = fmaf(w.x, hh.x, acc);
            acc = fmaf(w.y, hh.y, acc);
            acc = fmaf(w.z, hh.z, acc);
            acc = fmaf(w.w, hh.w, acc);
        }
        int o = t >> 1, d = t & 1;
        g_os[(o * BATCH + b) * 2 + d] = acc;
    }
}

// ============================================================
// Build fc4_w B-fragments (bf16x2), k exactly 0..1999 (no pad)
// idx = ((ks*4 + ntile)*32 + lane)*2 + reg
// element: n = lane>>2, k = ks*16 + reg*8 + (lane&3)*2
// ============================================================
__global__ void wf_kernel(const float* __restrict__ fc4_w)
{
    int idx = blockIdx.x * 256 + threadIdx.x;
    if (idx >= WF_U32) return;
    int reg   = idx & 1;
    int lane  = (idx >> 1) & 31;
    int ntile = (idx >> 6) & 3;
    int ks    = idx >> 8;
    int kl = ks * 16 + reg * 8 + (lane & 3) * 2;
    int j  = ntile * 8 + (lane >> 2);
    float v0 = fc4_w[j * 2000 + kl];
    float v1 = fc4_w[j * 2000 + kl + 1];
    uint32_t pk;
    asm("cvt.rn.bf16x2.f32 %0, %1, %2;" : "=r"(pk) : "f"(v1), "f"(v0)); // lo=v0, hi=v1
    g_wfrag[idx] = pk;
}

// ============================================================
// Main persistent simulation kernel: 128 CTAs x 512 thr, BT=32
// ============================================================
#define MMA_OP(C, Af, Bf)                                                      \
    asm volatile(                                                              \
        "mma.sync.aligned.m16n8k16.row.col.f32.bf16.bf16.f32 "                 \
        "{%0,%1,%2,%3}, {%4,%5,%6,%7}, {%8,%9}, {%0,%1,%2,%3};\n"              \
        : "+f"(C.x), "+f"(C.y), "+f"(C.z), "+f"(C.w)                           \
        : "r"(Af.x), "r"(Af.y), "r"(Af.z), "r"(Af.w), "r"(Bf.x), "r"(Bf.y))

extern "C" __global__ void __launch_bounds__(NTHR, 1)
sim_kernel(const float* __restrict__ x,
           const float* __restrict__ enc,
           const float* __restrict__ osc_bias,
           const float* __restrict__ dec,
           const float* __restrict__ fc4_b,
           const float* __restrict__ fc5_w,
           const float* __restrict__ fc5_b,
           float* __restrict__ out_l,     // [STEPS][B][4]
           float* __restrict__ out_act)   // [STEPS][B][2]
{
    extern __shared__ char smem[];
    uint32_t* s_af   = (uint32_t*)(smem + SM_AF);
    float2*   s_enc  = (float2*)  (smem + SM_ENC);
    float*    s_bias = (float*)   (smem + SM_BIAS);
    float*    s_dec  = (float*)   (smem + SM_DEC);
    float2*   s_os   = (float2*)  (smem + SM_OS);
    float4*   s_ch   = (float4*)  (smem + SM_CH);
    float*    s_part = (float*)   (smem + SM_PART);

    const int tid  = threadIdx.x;
    const int lane = tid & 31;
    const int wrp  = tid >> 5;
    const int b0   = blockIdx.x * BT;

    // ---- load constants into SMEM ----
    for (int i = tid; i < NOSC * NPER; i += NTHR) {
        int o = i / NPER, p = i - o * NPER;
        s_enc [o * ESTR + p] = ((const float2*)enc)[i];
        s_bias[o * ESTR + p] = osc_bias[i];
    }
    for (int i = tid; i < NOSC * 2 * NPER; i += NTHR) {
        int r = i / NPER, p = i - r * NPER;
        s_dec[r * ESTR + p] = dec[i];
    }
    for (int i = tid; i < NOSC * BT; i += NTHR) {
        int o = i >> 5, b = i & 31;
        s_os[o * OSSTR + b] = ((const float2*)g_os)[o * BATCH + b0 + b];
    }

    // ---- MMA warp role: (mtile, ntile, khalf) ----
    const int mt = wrp >> 3;          // 0..1
    const int nt = (wrp >> 1) & 3;    // 0..3
    const int kh = wrp & 1;           // 0..1
    const int ks0 = kh ? 63 : 0;
    const int nks = kh ? 62 : 63;

    // ---- epilogue per-lane constants (used by kh==0 warps) ----
    const int j0 = nt * 8 + ((lane & 3) << 1);
    const float b4j0  = fc4_b[j0],      b4j1  = fc4_b[j0 + 1];
    const float w50j0 = fc5_w[j0],      w50j1 = fc5_w[j0 + 1];
    const float w51j0 = fc5_w[32 + j0], w51j1 = fc5_w[32 + j0 + 1];

    // ---- warp0 limb state: one batch element per lane ----
    float th = 0.f, om = 0.f, l1s = 0.f, l2s = 0.f, dir0 = 0.f, dir1 = 0.f;
    float fc5b0 = 0.f, fc5b1 = 0.f;
    if (wrp == 0) {
        int b = b0 + lane;
        th  = x[b * 2];
        om  = 0.f;
        l1s = L0C - RC * th;
        l2s = L0C + RC * th;
        dir0 = g_direct[b * 2 + 0];
        dir1 = g_direct[b * 2 + 1];
        fc5b0 = fc5_b[0];
        fc5b1 = fc5_b[1];
    }

    // ---- fused-phase per-thread store constants (tb = lane always) ----
    const int tbb7  = lane & 7;
    const int tregm = (lane >> 3) & 1;
    const int tmt   = lane >> 4;
    const int mx    = ((tbb7 >> 1) & 3) << 2;   // xor swizzle for c-field
    const int stbase = (tbb7 << 4);             // within-chunk base

    // ---- MMA pointers (A swizzled base, B global) ----
    const uint32_t* afp = s_af + mt * 128 + ((lane * 4) ^ (((lane >> 3) & 3) << 2));
    const uint32_t* wfp = g_wfrag + (nt * 32 + lane) * 2;

    __syncthreads();

    for (int t = 0; t < STEPS; t++) {
        // ===== fused phase: all A fragments + deriv + oscillator update =====
        // task = o*32 + tb ; tb == lane, o uniform per warp per pass
        for (int task = tid; task < 1600; task += NTHR) {
            const int o  = task >> 5;
            const int tb = task & 31;
            float2 osv = s_os[o * OSSTR + tb];
            float s0 = 0.f, s1 = 0.f;
            const float4* ep  = (const float4*)(s_enc + o * ESTR);
            const float2* bp  = (const float2*)(s_bias + o * ESTR);
            const float2* d0p = (const float2*)(s_dec + (o * 2) * ESTR);
            const float2* d1p = (const float2*)(s_dec + (o * 2 + 1) * ESTR);
            const int kg0 = o * 40;
            #pragma unroll 4
            for (int pp = 0; pp < 20; pp++) {
                float4 e  = ep[pp];
                float2 bi = bp[pp];
                float a0 = fmaxf(fmaf(e.x, osv.x, fmaf(e.y, osv.y, bi.x)), 0.f);
                float a1 = fmaxf(fmaf(e.z, osv.x, fmaf(e.w, osv.y, bi.y)), 0.f);
                float2 dv0 = d0p[pp];
                float2 dv1 = d1p[pp];
                s0 = fmaf(dv0.x, a0, fmaf(dv0.y, a1, s0));
                s1 = fmaf(dv1.x, a0, fmaf(dv1.y, a1, s1));
                uint32_t pk;
                asm("cvt.rn.bf16x2.f32 %0, %1, %2;" : "=r"(pk) : "f"(a1), "f"(a0));
                int kg = kg0 + pp * 2;
                int ks = kg >> 4;
                int kk = kg & 15;
                int c  = (kk >> 1) & 3;
                int r  = ((kk >> 3) << 1) | tregm;
                s_af[(ks * 2 + tmt) * 128 + stbase + (((c << 2) ^ mx) | r)] = pk;
            }
            s_os[o * OSSTR + tb] = make_float2(osv.x + DTC * s0, osv.y + DTC * s1);
        }
        __syncthreads();   // bar1: A ready

        // ===== MMA: C[32x32] = A[32x2000] * W[2000x32], split over k-halves =====
        float4 acc[4];
        acc[0] = make_float4(0.f, 0.f, 0.f, 0.f);
        acc[1] = make_float4(0.f, 0.f, 0.f, 0.f);
        acc[2] = make_float4(0.f, 0.f, 0.f, 0.f);
        acc[3] = make_float4(0.f, 0.f, 0.f, 0.f);
        {
            const uint32_t* ap = afp + ks0 * 256;
            const uint32_t* wp = wfp + ks0 * 256;
            #pragma unroll 4
            for (int i = 0; i < nks; i++) {
                uint4 Af = *(const uint4*)(ap + i * 256);
                uint2 Bf = *(const uint2*)(wp + i * 256);
                MMA_OP(acc[i & 3], Af, Bf);
            }
        }
        float c0 = (acc[0].x + acc[1].x) + (acc[2].x + acc[3].x);
        float c1 = (acc[0].y + acc[1].y) + (acc[2].y + acc[3].y);
        float c2 = (acc[0].z + acc[1].z) + (acc[2].z + acc[3].z);
        float c3 = (acc[0].w + acc[1].w) + (acc[2].w + acc[3].w);

        if (kh) s_ch[(mt * 4 + nt) * 32 + lane] = make_float4(c0, c1, c2, c3);
        __syncthreads();   // bar2: k-half-1 partials ready

        if (kh == 0) {
            float4 pc = s_ch[(mt * 4 + nt) * 32 + lane];
            c0 += pc.x; c1 += pc.y; c2 += pc.z; c3 += pc.w;
            float b00 = fmaxf(c0 + b4j0, 0.f);
            float b01 = fmaxf(c1 + b4j1, 0.f);
            float b10 = fmaxf(c2 + b4j0, 0.f);
            float b11 = fmaxf(c3 + b4j1, 0.f);
            float p00 = fmaf(w50j0, b00, w50j1 * b01);
            float p01 = fmaf(w51j0, b00, w51j1 * b01);
            float p10 = fmaf(w50j0, b10, w50j1 * b11);
            float p11 = fmaf(w51j0, b10, w51j1 * b11);
            #pragma unroll
            for (int off = 1; off <= 2; off <<= 1) {
                p00 += __shfl_xor_sync(0xffffffffu, p00, off);
                p01 += __shfl_xor_sync(0xffffffffu, p01, off);
                p10 += __shfl_xor_sync(0xffffffffu, p10, off);
                p11 += __shfl_xor_sync(0xffffffffu, p11, off);
            }
            if ((lane & 3) == 0) {
                int m0 = mt * 16 + (lane >> 2);
                s_part[m0 * 8 + nt]           = p00;
                s_part[m0 * 8 + 4 + nt]       = p01;
                s_part[(m0 + 8) * 8 + nt]     = p10;
                s_part[(m0 + 8) * 8 + 4 + nt] = p11;
            }
        }
        __syncthreads();   // bar3: fc5 partials ready

        if (wrp == 0) {
            float4 q0 = *(const float4*)(s_part + lane * 8);
            float4 q1 = *(const float4*)(s_part + lane * 8 + 4);
            float A0 = fc5b0 + dir0 + ((q0.x + q0.y) + (q0.z + q0.w));
            float A1 = fc5b1 + dir1 + ((q1.x + q1.y) + (q1.z + q1.w));
            float f1 = fmaxf(A0, 0.f) * KMUS * fmaxf(l1s - LREST, 0.f);
            float f2 = fmaxf(A1, 0.f) * KMUS * fmaxf(l2s - LREST, 0.f);
            float domega = (RC * (f2 - f1) - DAMPC * om) / INERT;
            float dl1 = ((L0C - RC * th) - l1s) / TAUM;
            float dl2 = ((L0C + RC * th) - l2s) / TAUM;
            float pos = th + DTC * om;
            float vel = om + DTC * domega;
            l1s += DTC * dl1;
            l2s += DTC * dl2;
            bool inb = (pos > -HPI) && (pos < HPI);
            th = fminf(fmaxf(pos, -HPI), HPI);
            om = inb ? vel : 0.f;
            size_t lidx = (size_t)t * BATCH + b0 + lane;
            *(float4*)(out_l + lidx * 4)   = make_float4(th, om, l1s, l2s);
            *(float2*)(out_act + lidx * 2) = make_float2(A0, A1);
        }
    }
}

// ============================================================
// Launch
// ============================================================
extern "C" void kernel_launch(void* const* d_in, const int* in_sizes, int n_in,
                              void* d_out, int out_size)
{
    const float* x      = (const float*)d_in[0];
    const float* fc1_w  = (const float*)d_in[1];
    const float* fc1_b  = (const float*)d_in[2];
    const float* fc2_w  = (const float*)d_in[3];
    const float* fc2_b  = (const float*)d_in[4];
    const float* fc3_w  = (const float*)d_in[5];
    const float* fc3_b  = (const float*)d_in[6];
    const float* fcd_w  = (const float*)d_in[7];
    const float* fcd_b  = (const float*)d_in[8];
    const float* enc    = (const float*)d_in[9];
    const float* oscb   = (const float*)d_in[10];
    const float* dec    = (const float*)d_in[11];
    const float* fc4_w  = (const float*)d_in[12];
    const float* fc4_b  = (const float*)d_in[13];
    const float* fc5_w  = (const float*)d_in[14];
    const float* fc5_b  = (const float*)d_in[15];

    float* out   = (float*)d_out;
    float* out_l = out;                                   // STEPS*B*4
    float* out_a = out + (size_t)STEPS * BATCH * 4;       // STEPS*B*2

    cudaFuncSetAttribute(sim_kernel, cudaFuncAttributeMaxDynamicSharedMemorySize, SMEM_BYTES);

    pre_kernel<<<BATCH, 128>>>(x, fc1_w, fc1_b, fc2_w, fc2_b, fc3_w, fc3_b, fcd_w, fcd_b);
    wf_kernel<<<(WF_U32 + 255) / 256, 256>>>(fc4_w);
    sim_kernel<<<NCTA, NTHR, SMEM_BYTES>>>(x, enc, oscb, dec, fc4_b, fc5_w, fc5_b, out_l, out_a);
}

// round 7
// speedup vs baseline: 5.3673x; 1.0786x over previous
#include <cuda_runtime.h>
#include <cuda_bf16.h>
#include <cstdint>

// ---------------- problem constants ----------------
#define BATCH   4096
#define NOSC    50
#define NPER    40
#define STEPS   700
#define BT      32
#define NCTA    (BATCH/BT)   // 128
#define NTHR    512

#define DTC     0.001f
#define RC      0.02f
#define L0C     0.1f
#define INERT   0.001f
#define DAMPC   0.01f
#define KMUS    50.0f
#define LREST   0.05f
#define TAUM    0.05f
#define HPI     1.5707963267948966f

#define NKS     125                  // 2000 / 16 k-steps
// W fragment store: [ks(125)][ntile(4)][lane(32)][reg(2)] u32 (bf16x2)
#define WF_U32  (NKS*4*32*2)         // 32000

// ---------------- device scratch ----------------
__device__ float    g_os[NOSC * BATCH * 2];   // initial oscillator states [o][b][2]
__device__ float    g_direct[BATCH * 2];      // direct term [b][2]
__device__ uint32_t g_wfrag[WF_U32];          // fc4_w in MMA B-fragment layout

// ---------------- shared memory layout (bytes) ----------------
// A-frag: [ks(125)][mt(2)][128 u32 chunk]; word = (tbb7<<4)|((c<<2)^mx)|(rh<<1)|tregm
#define SM_AF    0         // 128000
#define SM_ENC   128000    // 16000 : enc as float4 per (o, p-pair)  [o*20+i]
#define SM_DC    144000    // 16000 : dec interleaved float4 (d0p0,d0p1,d1p0,d1p1)
#define SM_BS    160000    // 8000  : bias float2 per (o, p-pair)
#define SM_OS    168000    // 12800 : osc states float2 [o*32+b]
#define SM_CH    180800    // 4096  : partner C partials [mt*4+nt][lane] float4
#define SM_PART  184896    // 1024  : fc5 partials [m(32)][d(2)][nt(4)]
#define SMEM_BYTES 185920

// ============================================================
// Preamble: per-batch MLP -> direct, o0 (g_os), g_direct
// ============================================================
__global__ void pre_kernel(const float* __restrict__ x,
                           const float* __restrict__ fc1_w, const float* __restrict__ fc1_b,
                           const float* __restrict__ fc2_w, const float* __restrict__ fc2_b,
                           const float* __restrict__ fc3_w, const float* __restrict__ fc3_b,
                           const float* __restrict__ fcd_w, const float* __restrict__ fcd_b)
{
    __shared__ float sh[128];
    __shared__ float sh2[128];
    int t = threadIdx.x;
    int b = blockIdx.x;
    float x0 = x[b * 2 + 0];
    float x1 = x[b * 2 + 1];

    float h = fmaf(fc1_w[t * 2 + 0], x0, fmaf(fc1_w[t * 2 + 1], x1, fc1_b[t]));
    h = fmaxf(h, 0.0f);
    sh[t] = h;
    __syncthreads();

    const float4* h4 = (const float4*)sh;

    {
        float acc = fc2_b[t];
        const float4* w4 = (const float4*)&fc2_w[t * 128];
        #pragma unroll 8
        for (int i = 0; i < 32; i++) {
            float4 w = w4[i], hh = h4[i];
            acc = fmaf(w.x, hh.x, acc);
            acc = fmaf(w.y, hh.y, acc);
            acc = fmaf(w.z, hh.z, acc);
            acc = fmaf(w.w, hh.w, acc);
        }
        sh2[t] = fmaxf(acc, 0.0f);
    }

    if (t < 2) {
        float acc = fcd_b[t];
        const float4* w4 = (const float4*)&fcd_w[t * 128];
        #pragma unroll 8
        for (int i = 0; i < 32; i++) {
            float4 w = w4[i], hh = h4[i];
            acc = fmaf(w.x, hh.x, acc);
            acc = fmaf(w.y, hh.y, acc);
            acc = fmaf(w.z, hh.z, acc);
            acc = fmaf(w.w, hh.w, acc);
        }
        g_direct[b * 2 + t] = acc;
    }
    __syncthreads();

    if (t < 100) {
        float acc = fc3_b[t];
        const float4* w4 = (const float4*)&fc3_w[t * 128];
        const float4* g4 = (const float4*)sh2;
        #pragma unroll 8
        for (int i = 0; i < 32; i++) {
            float4 w = w4[i], hh = g4[i];
            acc = fmaf(w.x, hh.x, acc);
            acc = fmaf(w.y, hh.y, acc);
            acc = fmaf(w.z, hh.z, acc);
            acc = fmaf(w.w, hh.w, acc);
        }
        int o = t >> 1, d = t & 1;
        g_os[(o * BATCH + b) * 2 + d] = acc;
    }
}

// ============================================================
// Build fc4_w B-fragments (bf16x2), k 0..1999
// idx = ((ks*4 + ntile)*32 + lane)*2 + reg
// element: n = lane>>2, k = ks*16 + reg*8 + (lane&3)*2
// ============================================================
__global__ void wf_kernel(const float* __restrict__ fc4_w)
{
    int idx = blockIdx.x * 256 + threadIdx.x;
    if (idx >= WF_U32) return;
    int reg   = idx & 1;
    int lane  = (idx >> 1) & 31;
    int ntile = (idx >> 6) & 3;
    int ks    = idx >> 8;
    int kl = ks * 16 + reg * 8 + (lane & 3) * 2;
    int j  = ntile * 8 + (lane >> 2);
    float v0 = fc4_w[j * 2000 + kl];
    float v1 = fc4_w[j * 2000 + kl + 1];
    uint32_t pk;
    asm("cvt.rn.bf16x2.f32 %0, %1, %2;" : "=r"(pk) : "f"(v1), "f"(v0));
    g_wfrag[idx] = pk;
}

// ============================================================
// Main persistent simulation kernel: 128 CTAs x 512 thr, BT=32
// Two regions/step; single A buffer split at ks 65 (osc 26):
//  Region A(t): fused writes H1=A(t) ks65-124 ; MMA reads H0=A(t) ks0-64
//  Region B(t): fused writes H0=A(t+1) ks0-64 ; MMA reads H1=A(t) ks65-124
// ============================================================
#define MMA_OP(C, Af, Bf)                                                      \
    asm volatile(                                                              \
        "mma.sync.aligned.m16n8k16.row.col.f32.bf16.bf16.f32 "                 \
        "{%0,%1,%2,%3}, {%4,%5,%6,%7}, {%8,%9}, {%0,%1,%2,%3};\n"              \
        : "+f"(C.x), "+f"(C.y), "+f"(C.z), "+f"(C.w)                           \
        : "r"(Af.x), "r"(Af.y), "r"(Af.z), "r"(Af.w), "r"(Bf.x), "r"(Bf.y))

#define MMA_RANGE(KSB, KSN) {                                                  \
    const uint32_t* ap = afp + (KSB) * 256;                                    \
    const uint32_t* wp = wfp + (KSB) * 256;                                    \
    _Pragma("unroll 4")                                                        \
    for (int i = 0; i < (KSN); i++) {                                          \
        uint4 Af = *(const uint4*)(ap + i * 256);                              \
        uint2 Bf = *(const uint2*)(wp + i * 256);                              \
        MMA_OP(acc[i & 3], Af, Bf);                                            \
    }                                                                          \
}

#define FUSE(i, PA, OFF) {                                                     \
    float4 e = ep[i]; float4 dd = dp[i]; float2 bi = bp[i];                    \
    float a0 = fmaxf(fmaf(e.x, osx, fmaf(e.y, osy, bi.x)), 0.f);               \
    float a1 = fmaxf(fmaf(e.z, osx, fmaf(e.w, osy, bi.y)), 0.f);               \
    s0 = fmaf(dd.x, a0, fmaf(dd.y, a1, s0));                                   \
    s1 = fmaf(dd.z, a0, fmaf(dd.w, a1, s1));                                   \
    uint32_t pk;                                                               \
    asm("cvt.rn.bf16x2.f32 %0, %1, %2;" : "=r"(pk) : "f"(a1), "f"(a0));        \
    *(uint32_t*)((PA) + (OFF)) = pk;                                           \
}

// one oscillator-task: 40 activations -> A-frags + deriv -> os update
#define FUSED_PHASE(OBASE, NT)                                                 \
for (int task = tid; task < (NT); task += NTHR) {                              \
    const int o = (OBASE) + (task >> 5);                                       \
    float2 osv = s_os[o * 32 + lane];                                          \
    const float osx = osv.x, osy = osv.y;                                      \
    float s0 = 0.f, s1 = 0.f;                                                  \
    const float4* ep = s_enc4 + o * 20;                                        \
    const float4* dp = s_dc4  + o * 20;                                        \
    const float2* bp = s_bs2  + o * 20;                                        \
    const int ksb = (o * 5) >> 1;                                              \
    char* pa0 = paB0 + ksb * 1024;                                             \
    char* pa1 = paB1 + ksb * 1024;                                             \
    char* pa2 = paB2 + ksb * 1024;                                             \
    char* pa3 = paB3 + ksb * 1024;                                             \
    if ((o & 1) == 0) {                                                        \
        FUSE(0,pa0,0)    FUSE(1,pa1,0)    FUSE(2,pa2,0)    FUSE(3,pa3,0)       \
        FUSE(4,pa0,8)    FUSE(5,pa1,8)    FUSE(6,pa2,8)    FUSE(7,pa3,8)       \
        FUSE(8,pa0,1024) FUSE(9,pa1,1024) FUSE(10,pa2,1024) FUSE(11,pa3,1024)  \
        FUSE(12,pa0,1032) FUSE(13,pa1,1032) FUSE(14,pa2,1032) FUSE(15,pa3,1032)\
        FUSE(16,pa0,2048) FUSE(17,pa1,2048) FUSE(18,pa2,2048) FUSE(19,pa3,2048)\
    } else {                                                                   \
        FUSE(0,pa0,8)    FUSE(1,pa1,8)    FUSE(2,pa2,8)    FUSE(3,pa3,8)       \
        FUSE(4,pa0,1024) FUSE(5,pa1,1024) FUSE(6,pa2,1024) FUSE(7,pa3,1024)    \
        FUSE(8,pa0,1032) FUSE(9,pa1,1032) FUSE(10,pa2,1032) FUSE(11,pa3,1032)  \
        FUSE(12,pa0,2048) FUSE(13,pa1,2048) FUSE(14,pa2,2048) FUSE(15,pa3,2048)\
        FUSE(16,pa0,2056) FUSE(17,pa1,2056) FUSE(18,pa2,2056) FUSE(19,pa3,2056)\
    }                                                                          \
    s_os[o * 32 + lane] = make_float2(osx + DTC * s0, osy + DTC * s1);         \
}

extern "C" __global__ void __launch_bounds__(NTHR, 1)
sim_kernel(const float* __restrict__ x,
           const float* __restrict__ enc,
           const float* __restrict__ osc_bias,
           const float* __restrict__ dec,
           const float* __restrict__ fc4_b,
           const float* __restrict__ fc5_w,
           const float* __restrict__ fc5_b,
           float* __restrict__ out_l,     // [STEPS][B][4]
           float* __restrict__ out_act)   // [STEPS][B][2]
{
    extern __shared__ char smem[];
    float4* s_enc4 = (float4*)(smem + SM_ENC);
    float4* s_dc4  = (float4*)(smem + SM_DC);
    float2* s_bs2  = (float2*)(smem + SM_BS);
    float2* s_os   = (float2*)(smem + SM_OS);
    float4* s_ch   = (float4*)(smem + SM_CH);
    float*  s_part = (float*) (smem + SM_PART);

    const int tid  = threadIdx.x;
    const int lane = tid & 31;
    const int wrp  = tid >> 5;
    const int b0   = blockIdx.x * BT;

    // ---- load constants into SMEM ----
    for (int i = tid; i < 1000; i += NTHR) s_enc4[i] = ((const float4*)enc)[i];
    for (int i = tid; i < 1000; i += NTHR) {
        int o = i / 20, pp = i - o * 20;
        float d00 = dec[o * 80 +      pp * 2];
        float d01 = dec[o * 80 +      pp * 2 + 1];
        float d10 = dec[o * 80 + 40 + pp * 2];
        float d11 = dec[o * 80 + 40 + pp * 2 + 1];
        s_dc4[i] = make_float4(d00, d01, d10, d11);
    }
    for (int i = tid; i < 1000; i += NTHR) s_bs2[i] = ((const float2*)osc_bias)[i];
    for (int i = tid; i < NOSC * BT; i += NTHR) {
        int o = i >> 5, b = i & 31;
        s_os[o * 32 + b] = ((const float2*)g_os)[o * BATCH + b0 + b];
    }

    // ---- MMA warp role: (mt, nt, s) ----
    const int mt = wrp >> 3;          // 0..1
    const int nt = (wrp >> 1) & 3;    // 0..3
    const int sp = wrp & 1;           // k-split partner id

    // ---- fused store address precompute (swizzled) ----
    const int tbb7  = lane & 7;
    const int tregm = (lane >> 3) & 1;
    const int tmt   = lane >> 4;
    const int mxv   = ((tbb7 >> 1) & 3) << 2;
    char* paB0 = smem + SM_AF + 4 * (tmt * 128 + (tbb7 << 4) + ((0 ^ mxv)) + tregm);
    char* paB1 = smem + SM_AF + 4 * (tmt * 128 + (tbb7 << 4) + ((4 ^ mxv)) + tregm);
    char* paB2 = smem + SM_AF + 4 * (tmt * 128 + (tbb7 << 4) + ((8 ^ mxv)) + tregm);
    char* paB3 = smem + SM_AF + 4 * (tmt * 128 + (tbb7 << 4) + ((12 ^ mxv)) + tregm);

    // ---- MMA pointers ----
    const uint32_t* afp = (const uint32_t*)(smem + SM_AF) + mt * 128
                        + ((lane * 4) ^ (((lane >> 3) & 3) << 2));
    const uint32_t* wfp = g_wfrag + (nt * 32 + lane) * 2;

    // ---- epilogue per-lane constants ----
    const int j0 = nt * 8 + ((lane & 3) << 1);
    const float b4j0  = fc4_b[j0],      b4j1  = fc4_b[j0 + 1];
    const float w50j0 = fc5_w[j0],      w50j1 = fc5_w[j0 + 1];
    const float w51j0 = fc5_w[32 + j0], w51j1 = fc5_w[32 + j0 + 1];

    // ---- warp0 limb state: one batch element per lane ----
    float th = 0.f, om = 0.f, l1s = 0.f, l2s = 0.f, dir0 = 0.f, dir1 = 0.f;
    float fc5b0 = 0.f, fc5b1 = 0.f;
    if (wrp == 0) {
        int b = b0 + lane;
        th  = x[b * 2];
        om  = 0.f;
        l1s = L0C - RC * th;
        l2s = L0C + RC * th;
        dir0 = g_direct[b * 2 + 0];
        dir1 = g_direct[b * 2 + 1];
        fc5b0 = fc5_b[0];
        fc5b1 = fc5_b[1];
    }

    __syncthreads();

    // ---- prologue: A(0) H0 (osc 0..25) ----
    FUSED_PHASE(0, 832);
    __syncthreads();

    float4 acc[4];
    #pragma unroll
    for (int q = 0; q < 4; q++) acc[q] = make_float4(0.f, 0.f, 0.f, 0.f);
    float cc0 = 0.f, cc1 = 0.f, cc2 = 0.f, cc3 = 0.f;

    for (int t = 0; t < STEPS; t++) {
        // ===== Region A(t) =====
        // epilogue-combine for C(t-1) (s==0 warps)
        if (t > 0 && sp == 0) {
            float4 pc = s_ch[(mt * 4 + nt) * 32 + lane];
            float c0 = cc0 + pc.x, c1 = cc1 + pc.y, c2 = cc2 + pc.z, c3 = cc3 + pc.w;
            float b00 = fmaxf(c0 + b4j0, 0.f);
            float b01 = fmaxf(c1 + b4j1, 0.f);
            float b10 = fmaxf(c2 + b4j0, 0.f);
            float b11 = fmaxf(c3 + b4j1, 0.f);
            float p00 = fmaf(w50j0, b00, w50j1 * b01);
            float p01 = fmaf(w51j0, b00, w51j1 * b01);
            float p10 = fmaf(w50j0, b10, w50j1 * b11);
            float p11 = fmaf(w51j0, b10, w51j1 * b11);
            #pragma unroll
            for (int off = 1; off <= 2; off <<= 1) {
                p00 += __shfl_xor_sync(0xffffffffu, p00, off);
                p01 += __shfl_xor_sync(0xffffffffu, p01, off);
                p10 += __shfl_xor_sync(0xffffffffu, p10, off);
                p11 += __shfl_xor_sync(0xffffffffu, p11, off);
            }
            if ((lane & 3) == 0) {
                int m0 = mt * 16 + (lane >> 2);
                s_part[m0 * 8 + nt]           = p00;
                s_part[m0 * 8 + 4 + nt]       = p01;
                s_part[(m0 + 8) * 8 + nt]     = p10;
                s_part[(m0 + 8) * 8 + 4 + nt] = p11;
            }
        }
        // fused: A(t) H1 (osc 26..49)
        FUSED_PHASE(26, 768);
        // MMA: C(t) over H0 (ks 0..64)
        if (sp == 0) { MMA_RANGE(0, 33) } else { MMA_RANGE(33, 32) }
        __syncthreads();

        // ===== Region B(t) =====
        // limb(t-1) by warp0
        if (t > 0 && wrp == 0) {
            float4 q0 = *(const float4*)(s_part + lane * 8);
            float4 q1 = *(const float4*)(s_part + lane * 8 + 4);
            float A0 = fc5b0 + dir0 + ((q0.x + q0.y) + (q0.z + q0.w));
            float A1 = fc5b1 + dir1 + ((q1.x + q1.y) + (q1.z + q1.w));
            float f1 = fmaxf(A0, 0.f) * KMUS * fmaxf(l1s - LREST, 0.f);
            float f2 = fmaxf(A1, 0.f) * KMUS * fmaxf(l2s - LREST, 0.f);
            float domega = (RC * (f2 - f1) - DAMPC * om) / INERT;
            float dl1 = ((L0C - RC * th) - l1s) / TAUM;
            float dl2 = ((L0C + RC * th) - l2s) / TAUM;
            float pos = th + DTC * om;
            float vel = om + DTC * domega;
            l1s += DTC * dl1;
            l2s += DTC * dl2;
            bool inb = (pos > -HPI) && (pos < HPI);
            th = fminf(fmaxf(pos, -HPI), HPI);
            om = inb ? vel : 0.f;
            size_t lidx = (size_t)(t - 1) * BATCH + b0 + lane;
            *(float4*)(out_l + lidx * 4)   = make_float4(th, om, l1s, l2s);
            *(float2*)(out_act + lidx * 2) = make_float2(A0, A1);
        }
        // fused: A(t+1) H0 (osc 0..25)
        if (t < STEPS - 1) { FUSED_PHASE(0, 832) }
        // MMA: C(t) over H1 (ks 65..124)
        if (sp == 0) { MMA_RANGE(65, 30) } else { MMA_RANGE(95, 30) }
        // extract C(t) contribution
        {
            float e0 = (acc[0].x + acc[1].x) + (acc[2].x + acc[3].x);
            float e1 = (acc[0].y + acc[1].y) + (acc[2].y + acc[3].y);
            float e2 = (acc[0].z + acc[1].z) + (acc[2].z + acc[3].z);
            float e3 = (acc[0].w + acc[1].w) + (acc[2].w + acc[3].w);
            if (sp) s_ch[(mt * 4 + nt) * 32 + lane] = make_float4(e0, e1, e2, e3);
            else { cc0 = e0; cc1 = e1; cc2 = e2; cc3 = e3; }
            #pragma unroll
            for (int q = 0; q < 4; q++) acc[q] = make_float4(0.f, 0.f, 0.f, 0.f);
        }
        __syncthreads();
    }

    // ===== drain: epilogue + limb for step STEPS-1 =====
    if (sp == 0) {
        float4 pc = s_ch[(mt * 4 + nt) * 32 + lane];
        float c0 = cc0 + pc.x, c1 = cc1 + pc.y, c2 = cc2 + pc.z, c3 = cc3 + pc.w;
        float b00 = fmaxf(c0 + b4j0, 0.f);
        float b01 = fmaxf(c1 + b4j1, 0.f);
        float b10 = fmaxf(c2 + b4j0, 0.f);
        float b11 = fmaxf(c3 + b4j1, 0.f);
        float p00 = fmaf(w50j0, b00, w50j1 * b01);
        float p01 = fmaf(w51j0, b00, w51j1 * b01);
        float p10 = fmaf(w50j0, b10, w50j1 * b11);
        float p11 = fmaf(w51j0, b10, w51j1 * b11);
        #pragma unroll
        for (int off = 1; off <= 2; off <<= 1) {
            p00 += __shfl_xor_sync(0xffffffffu, p00, off);
            p01 += __shfl_xor_sync(0xffffffffu, p01, off);
            p10 += __shfl_xor_sync(0xffffffffu, p10, off);
            p11 += __shfl_xor_sync(0xffffffffu, p11, off);
        }
        if ((lane & 3) == 0) {
            int m0 = mt * 16 + (lane >> 2);
            s_part[m0 * 8 + nt]           = p00;
            s_part[m0 * 8 + 4 + nt]       = p01;
            s_part[(m0 + 8) * 8 + nt]     = p10;
            s_part[(m0 + 8) * 8 + 4 + nt] = p11;
        }
    }
    __syncthreads();
    if (wrp == 0) {
        float4 q0 = *(const float4*)(s_part + lane * 8);
        float4 q1 = *(const float4*)(s_part + lane * 8 + 4);
        float A0 = fc5b0 + dir0 + ((q0.x + q0.y) + (q0.z + q0.w));
        float A1 = fc5b1 + dir1 + ((q1.x + q1.y) + (q1.z + q1.w));
        float f1 = fmaxf(A0, 0.f) * KMUS * fmaxf(l1s - LREST, 0.f);
        float f2 = fmaxf(A1, 0.f) * KMUS * fmaxf(l2s - LREST, 0.f);
        float domega = (RC * (f2 - f1) - DAMPC * om) / INERT;
        float dl1 = ((L0C - RC * th) - l1s) / TAUM;
        float dl2 = ((L0C + RC * th) - l2s) / TAUM;
        float pos = th + DTC * om;
        float vel = om + DTC * domega;
        l1s += DTC * dl1;
        l2s += DTC * dl2;
        bool inb = (pos > -HPI) && (pos < HPI);
        th = fminf(fmaxf(pos, -HPI), HPI);
        om = inb ? vel : 0.f;
        size_t lidx = (size_t)(STEPS - 1) * BATCH + b0 + lane;
        *(float4*)(out_l + lidx * 4)   = make_float4(th, om, l1s, l2s);
        *(float2*)(out_act + lidx * 2) = make_float2(A0, A1);
    }
}

// ============================================================
// Launch
// ============================================================
extern "C" void kernel_launch(void* const* d_in, const int* in_sizes, int n_in,
                              void* d_out, int out_size)
{
    const float* x      = (const float*)d_in[0];
    const float* fc1_w  = (const float*)d_in[1];
    const float* fc1_b  = (const float*)d_in[2];
    const float* fc2_w  = (const float*)d_in[3];
    const float* fc2_b  = (const float*)d_in[4];
    const float* fc3_w  = (const float*)d_in[5];
    const float* fc3_b  = (const float*)d_in[6];
    const float* fcd_w  = (const float*)d_in[7];
    const float* fcd_b  = (const float*)d_in[8];
    const float* enc    = (const float*)d_in[9];
    const float* oscb   = (const float*)d_in[10];
    const float* dec    = (const float*)d_in[11];
    const float* fc4_w  = (const float*)d_in[12];
    const float* fc4_b  = (const float*)d_in[13];
    const float* fc5_w  = (const float*)d_in[14];
    const float* fc5_b  = (const float*)d_in[15];

    float* out   = (float*)d_out;
    float* out_l = out;                                   // STEPS*B*4
    float* out_a = out + (size_t)STEPS * BATCH * 4;       // STEPS*B*2

    cudaFuncSetAttribute(sim_kernel, cudaFuncAttributeMaxDynamicSharedMemorySize, SMEM_BYTES);

    pre_kernel<<<BATCH, 128>>>(x, fc1_w, fc1_b, fc2_w, fc2_b, fc3_w, fc3_b, fcd_w, fcd_b);
    wf_kernel<<<(WF_U32 + 255) / 256, 256>>>(fc4_w);
    sim_kernel<<<NCTA, NTHR, SMEM_BYTES>>>(x, enc, oscb, dec, fc4_b, fc5_w, fc5_b, out_l, out_a);
}

// round 8
// speedup vs baseline: 7.3880x; 1.3765x over previous
#include <cuda_runtime.h>
#include <cuda_bf16.h>
#include <cstdint>

// ---------------- problem constants ----------------
#define BATCH   4096
#define NOSC    50
#define NPER    40
#define STEPS   700
#define BT      32
#define NCTA    (BATCH/BT)   // 128
#define NTHR    512

#define DTC     0.001f
#define RC      0.02f
#define L0C     0.1f
#define INERT   0.001f
#define DAMPC   0.01f
#define KMUS    50.0f
#define LREST   0.05f
#define TAUM    0.05f
#define HPI     1.5707963267948966f

#define NKS     125
// W fragment store: [ks(125)][lane(32)][nt(4)][reg(2)] u32 (bf16x2)
#define WF_U32  (NKS*32*4*2)   // 32000

// ---------------- device scratch ----------------
__device__ float    g_os[NOSC * BATCH * 2];
__device__ float    g_direct[BATCH * 2];
__device__ uint32_t g_wfrag[WF_U32];

// ---------------- shared memory layout (bytes) ----------------
// A-frag: [ks(125)][mt(2)][512B chunk]; word = (tbb7<<4)|((c<<2)^mx)|((rh^tmt)<<1)|tregm
#define SM_AF    0         // 128000
#define SM_ED    128000    // 16000 : per (o,pp): uint4 = (ex2,ey2,dA2,dB2) bf16x2
#define SM_BS    144000    // 4000  : per (o,pp): bf16x2 bias
#define SM_OS    148000    // 12800 : osc states float2 [o*32+b] (fp32 state)
#define SM_CP    160800    // 32768 : C partials [(mt*8+s)*4+nt][lane] float4
#define SM_PART  193568    // 1024  : fc5 partials [m(32)][d(2)][nt(4)]
#define SMEM_BYTES 194592

// ============================================================
// Preamble: per-batch MLP -> direct, o0 (g_os), g_direct
// ============================================================
__global__ void pre_kernel(const float* __restrict__ x,
                           const float* __restrict__ fc1_w, const float* __restrict__ fc1_b,
                           const float* __restrict__ fc2_w, const float* __restrict__ fc2_b,
                           const float* __restrict__ fc3_w, const float* __restrict__ fc3_b,
                           const float* __restrict__ fcd_w, const float* __restrict__ fcd_b)
{
    __shared__ float sh[128];
    __shared__ float sh2[128];
    int t = threadIdx.x;
    int b = blockIdx.x;
    float x0 = x[b * 2 + 0];
    float x1 = x[b * 2 + 1];

    float h = fmaf(fc1_w[t * 2 + 0], x0, fmaf(fc1_w[t * 2 + 1], x1, fc1_b[t]));
    h = fmaxf(h, 0.0f);
    sh[t] = h;
    __syncthreads();

    const float4* h4 = (const float4*)sh;

    {
        float acc = fc2_b[t];
        const float4* w4 = (const float4*)&fc2_w[t * 128];
        #pragma unroll 8
        for (int i = 0; i < 32; i++) {
            float4 w = w4[i], hh = h4[i];
            acc = fmaf(w.x, hh.x, acc);
            acc = fmaf(w.y, hh.y, acc);
            acc = fmaf(w.z, hh.z, acc);
            acc = fmaf(w.w, hh.w, acc);
        }
        sh2[t] = fmaxf(acc, 0.0f);
    }

    if (t < 2) {
        float acc = fcd_b[t];
        const float4* w4 = (const float4*)&fcd_w[t * 128];
        #pragma unroll 8
        for (int i = 0; i < 32; i++) {
            float4 w = w4[i], hh = h4[i];
            acc = fmaf(w.x, hh.x, acc);
            acc = fmaf(w.y, hh.y, acc);
            acc = fmaf(w.z, hh.z, acc);
            acc = fmaf(w.w, hh.w, acc);
        }
        g_direct[b * 2 + t] = acc;
    }
    __syncthreads();

    if (t < 100) {
        float acc = fc3_b[t];
        const float4* w4 = (const float4*)&fc3_w[t * 128];
        const float4* g4 = (const float4*)sh2;
        #pragma unroll 8
        for (int i = 0; i < 32; i++) {
            float4 w = w4[i], hh = g4[i];
            acc = fmaf(w.x, hh.x, acc);
            acc = fmaf(w.y, hh.y, acc);
            acc = fmaf(w.z, hh.z, acc);
            acc = fmaf(w.w, hh.w, acc);
        }
        int o = t >> 1, d = t & 1;
        g_os[(o * BATCH + b) * 2 + d] = acc;
    }
}

// ============================================================
// Build fc4_w B-fragments, layout [ks][lane][nt][reg]
// element: n = lane>>2, k = ks*16 + reg*8 + (lane&3)*2, j = nt*8 + n
// ============================================================
__global__ void wf_kernel(const float* __restrict__ fc4_w)
{
    int idx = blockIdx.x * 256 + threadIdx.x;
    if (idx >= WF_U32) return;
    int reg  = idx & 1;
    int nt   = (idx >> 1) & 3;
    int lane = (idx >> 3) & 31;
    int ks   = idx >> 8;
    int kl = ks * 16 + reg * 8 + (lane & 3) * 2;
    int j  = nt * 8 + (lane >> 2);
    float v0 = fc4_w[j * 2000 + kl];
    float v1 = fc4_w[j * 2000 + kl + 1];
    uint32_t pk;
    asm("cvt.rn.bf16x2.f32 %0, %1, %2;" : "=r"(pk) : "f"(v1), "f"(v0));
    g_wfrag[idx] = pk;
}

// ============================================================
// Main persistent simulation kernel: 128 CTAs x 512 thr
// ============================================================
#define MMA_OP(C, A0,A1,A2,A3, Bx,By)                                          \
    asm volatile(                                                              \
        "mma.sync.aligned.m16n8k16.row.col.f32.bf16.bf16.f32 "                 \
        "{%0,%1,%2,%3}, {%4,%5,%6,%7}, {%8,%9}, {%0,%1,%2,%3};\n"              \
        : "+f"(C.x), "+f"(C.y), "+f"(C.z), "+f"(C.w)                           \
        : "r"(A0), "r"(A1), "r"(A2), "r"(A3), "r"(Bx), "r"(By))

#define MMA_LOOP(KSB, KSN, FA,FB,FC,FD) {                                      \
    const char* ab = afB + (KSB) * 1024;                                       \
    const char* bb = wfB + (KSB) * 1024;                                       \
    _Pragma("unroll 4")                                                        \
    for (int i = 0; i < (KSN); i++) {                                          \
        uint4 Af = *(const uint4*)(ab + i * 1024);                             \
        uint4 B0 = *(const uint4*)(bb + i * 1024);                             \
        uint4 B1 = *(const uint4*)(bb + i * 1024 + 16);                        \
        MMA_OP(acc0, Af.FA, Af.FB, Af.FC, Af.FD, B0.x, B0.y);                  \
        MMA_OP(acc1, Af.FA, Af.FB, Af.FC, Af.FD, B0.z, B0.w);                  \
        MMA_OP(acc2, Af.FA, Af.FB, Af.FC, Af.FD, B1.x, B1.y);                  \
        MMA_OP(acc3, Af.FA, Af.FB, Af.FC, Af.FD, B1.z, B1.w);                  \
    } }

#define MMA_SEG(KSB, KSN)                                                      \
    if (mt == 0) { MMA_LOOP(KSB, KSN, x, y, z, w) }                            \
    else         { MMA_LOOP(KSB, KSN, z, w, x, y) }

// FUSE: 2 activation elems in bf16x2; RH is a literal 0/1
#define FUSE(I, BV, PA, KO, RH, S0, S1) {                                      \
    uint4 ed = edp[I];                                                         \
    uint32_t v_, a_;                                                           \
    asm("fma.rn.bf16x2 %0, %1, %2, %3;" : "=r"(v_) : "r"(ed.y), "r"(osy2), "r"(BV)); \
    asm("fma.rn.bf16x2 %0, %1, %2, %3;" : "=r"(v_) : "r"(ed.x), "r"(osx2), "r"(v_)); \
    asm("max.bf16x2 %0, %1, %2;" : "=r"(a_) : "r"(v_), "r"(zero_));            \
    asm("fma.rn.bf16x2 %0, %1, %2, %0;" : "+r"(S0) : "r"(ed.z), "r"(a_));      \
    asm("fma.rn.bf16x2 %0, %1, %2, %0;" : "+r"(S1) : "r"(ed.w), "r"(a_));      \
    *(uint32_t*)((PA) + (KO) + ((RH) ? F1 : F0)) = a_;                         \
}

#define FUSED_PHASE(OBASE, NTASK)                                              \
for (int task = tid; task < (NTASK); task += NTHR) {                           \
    const int o = (OBASE) + (task >> 5);                                       \
    float2 osv = s_os[o * 32 + lane];                                          \
    uint32_t osx2, osy2;                                                       \
    asm("cvt.rn.bf16x2.f32 %0, %1, %1;" : "=r"(osx2) : "f"(osv.x));            \
    asm("cvt.rn.bf16x2.f32 %0, %1, %1;" : "=r"(osy2) : "f"(osv.y));            \
    const uint4* edp = s_ed4 + o * 20;                                         \
    const uint4* bsp = (const uint4*)(s_bs + o * 20);                          \
    uint4 BQ0 = bsp[0], BQ1 = bsp[1], BQ2 = bsp[2], BQ3 = bsp[3], BQ4 = bsp[4];\
    uint32_t s0p = 0, s0q = 0, s1p = 0, s1q = 0;                               \
    const int ksoff = ((o * 5) >> 1) * 1024;                                   \
    char* q0 = pa0 + ksoff;                                                    \
    char* q1 = pa1 + ksoff;                                                    \
    char* q2 = pa2 + ksoff;                                                    \
    char* q3 = pa3 + ksoff;                                                    \
    if ((o & 1) == 0) {                                                        \
        FUSE(0,  BQ0.x, q0, 0,    0, s0p, s1p) FUSE(1,  BQ0.y, q1, 0,    0, s0q, s1q) \
        FUSE(2,  BQ0.z, q2, 0,    0, s0p, s1p) FUSE(3,  BQ0.w, q3, 0,    0, s0q, s1q) \
        FUSE(4,  BQ1.x, q0, 0,    1, s0p, s1p) FUSE(5,  BQ1.y, q1, 0,    1, s0q, s1q) \
        FUSE(6,  BQ1.z, q2, 0,    1, s0p, s1p) FUSE(7,  BQ1.w, q3, 0,    1, s0q, s1q) \
        FUSE(8,  BQ2.x, q0, 1024, 0, s0p, s1p) FUSE(9,  BQ2.y, q1, 1024, 0, s0q, s1q) \
        FUSE(10, BQ2.z, q2, 1024, 0, s0p, s1p) FUSE(11, BQ2.w, q3, 1024, 0, s0q, s1q) \
        FUSE(12, BQ3.x, q0, 1024, 1, s0p, s1p) FUSE(13, BQ3.y, q1, 1024, 1, s0q, s1q) \
        FUSE(14, BQ3.z, q2, 1024, 1, s0p, s1p) FUSE(15, BQ3.w, q3, 1024, 1, s0q, s1q) \
        FUSE(16, BQ4.x, q0, 2048, 0, s0p, s1p) FUSE(17, BQ4.y, q1, 2048, 0, s0q, s1q) \
        FUSE(18, BQ4.z, q2, 2048, 0, s0p, s1p) FUSE(19, BQ4.w, q3, 2048, 0, s0q, s1q) \
    } else {                                                                   \
        FUSE(0,  BQ0.x, q0, 0,    1, s0p, s1p) FUSE(1,  BQ0.y, q1, 0,    1, s0q, s1q) \
        FUSE(2,  BQ0.z, q2, 0,    1, s0p, s1p) FUSE(3,  BQ0.w, q3, 0,    1, s0q, s1q) \
        FUSE(4,  BQ1.x, q0, 1024, 0, s0p, s1p) FUSE(5,  BQ1.y, q1, 1024, 0, s0q, s1q) \
        FUSE(6,  BQ1.z, q2, 1024, 0, s0p, s1p) FUSE(7,  BQ1.w, q3, 1024, 0, s0q, s1q) \
        FUSE(8,  BQ2.x, q0, 1024, 1, s0p, s1p) FUSE(9,  BQ2.y, q1, 1024, 1, s0q, s1q) \
        FUSE(10, BQ2.z, q2, 1024, 1, s0p, s1p) FUSE(11, BQ2.w, q3, 1024, 1, s0q, s1q) \
        FUSE(12, BQ3.x, q0, 2048, 0, s0p, s1p) FUSE(13, BQ3.y, q1, 2048, 0, s0q, s1q) \
        FUSE(14, BQ3.z, q2, 2048, 0, s0p, s1p) FUSE(15, BQ3.w, q3, 2048, 0, s0q, s1q) \
        FUSE(16, BQ4.x, q0, 2048, 1, s0p, s1p) FUSE(17, BQ4.y, q1, 2048, 1, s0q, s1q) \
        FUSE(18, BQ4.z, q2, 2048, 1, s0p, s1p) FUSE(19, BQ4.w, q3, 2048, 1, s0q, s1q) \
    }                                                                          \
    float2 u0 = __bfloat1622float2(*(__nv_bfloat162*)&s0p);                    \
    float2 u1 = __bfloat1622float2(*(__nv_bfloat162*)&s0q);                    \
    float2 w0 = __bfloat1622float2(*(__nv_bfloat162*)&s1p);                    \
    float2 w1 = __bfloat1622float2(*(__nv_bfloat162*)&s1q);                    \
    float d0 = (u0.x + u0.y) + (u1.x + u1.y);                                  \
    float d1 = (w0.x + w0.y) + (w1.x + w1.y);                                  \
    s_os[o * 32 + lane] = make_float2(osv.x + DTC * d0, osv.y + DTC * d1);     \
}

#define EPILOGUE_COMBINE() {                                                   \
    const float4* cp = (const float4*)(smem + SM_CP) + (emt * 8 * 4 + ent) * 32 + lane; \
    float4 cs = cp[0];                                                         \
    _Pragma("unroll")                                                          \
    for (int s2 = 1; s2 < 8; s2++) {                                           \
        float4 v = cp[s2 * 128];                                               \
        cs.x += v.x; cs.y += v.y; cs.z += v.z; cs.w += v.w;                    \
    }                                                                          \
    float b00 = fmaxf(cs.x + b4j0, 0.f);                                       \
    float b01 = fmaxf(cs.y + b4j1, 0.f);                                       \
    float b10 = fmaxf(cs.z + b4j0, 0.f);                                       \
    float b11 = fmaxf(cs.w + b4j1, 0.f);                                       \
    float p00 = fmaf(w50j0, b00, w50j1 * b01);                                 \
    float p01 = fmaf(w51j0, b00, w51j1 * b01);                                 \
    float p10 = fmaf(w50j0, b10, w50j1 * b11);                                 \
    float p11 = fmaf(w51j0, b10, w51j1 * b11);                                 \
    _Pragma("unroll")                                                          \
    for (int off = 1; off <= 2; off <<= 1) {                                   \
        p00 += __shfl_xor_sync(0xffffffffu, p00, off);                         \
        p01 += __shfl_xor_sync(0xffffffffu, p01, off);                         \
        p10 += __shfl_xor_sync(0xffffffffu, p10, off);                         \
        p11 += __shfl_xor_sync(0xffffffffu, p11, off);                         \
    }                                                                          \
    if ((lane & 3) == 0) {                                                     \
        int m0 = emt * 16 + (lane >> 2);                                       \
        s_part[m0 * 8 + ent]           = p00;                                  \
        s_part[m0 * 8 + 4 + ent]       = p01;                                  \
        s_part[(m0 + 8) * 8 + ent]     = p10;                                  \
        s_part[(m0 + 8) * 8 + 4 + ent] = p11;                                  \
    }                                                                          \
}

#define LIMB_STEP(TOUT) {                                                      \
    float4 qq0 = *(const float4*)(s_part + lane * 8);                          \
    float4 qq1 = *(const float4*)(s_part + lane * 8 + 4);                      \
    float A0 = fc5b0 + dir0 + ((qq0.x + qq0.y) + (qq0.z + qq0.w));             \
    float A1 = fc5b1 + dir1 + ((qq1.x + qq1.y) + (qq1.z + qq1.w));             \
    float f1 = fmaxf(A0, 0.f) * KMUS * fmaxf(l1s - LREST, 0.f);                \
    float f2 = fmaxf(A1, 0.f) * KMUS * fmaxf(l2s - LREST, 0.f);                \
    float domega = (RC * (f2 - f1) - DAMPC * om) / INERT;                      \
    float dl1 = ((L0C - RC * th) - l1s) / TAUM;                                \
    float dl2 = ((L0C + RC * th) - l2s) / TAUM;                                \
    float pos = th + DTC * om;                                                 \
    float vel = om + DTC * domega;                                             \
    l1s += DTC * dl1;                                                          \
    l2s += DTC * dl2;                                                          \
    bool inb = (pos > -HPI) && (pos < HPI);                                    \
    th = fminf(fmaxf(pos, -HPI), HPI);                                         \
    om = inb ? vel : 0.f;                                                      \
    size_t lidx = (size_t)(TOUT) * BATCH + b0 + lane;                          \
    *(float4*)(out_l + lidx * 4)   = make_float4(th, om, l1s, l2s);            \
    *(float2*)(out_act + lidx * 2) = make_float2(A0, A1);                      \
}

extern "C" __global__ void __launch_bounds__(NTHR, 1)
sim_kernel(const float* __restrict__ x,
           const float* __restrict__ enc,
           const float* __restrict__ osc_bias,
           const float* __restrict__ dec,
           const float* __restrict__ fc4_b,
           const float* __restrict__ fc5_w,
           const float* __restrict__ fc5_b,
           float* __restrict__ out_l,
           float* __restrict__ out_act)
{
    extern __shared__ char smem[];
    uint4*    s_ed4  = (uint4*)   (smem + SM_ED);
    uint32_t* s_bs   = (uint32_t*)(smem + SM_BS);
    float2*   s_os   = (float2*)  (smem + SM_OS);
    float*    s_part = (float*)   (smem + SM_PART);

    const int tid  = threadIdx.x;
    const int lane = tid & 31;
    const int wrp  = tid >> 5;
    const int b0   = blockIdx.x * BT;
    const uint32_t zero_ = 0u;

    // ---- build packed enc/dec/bias tables ----
    for (int i = tid; i < 1000; i += NTHR) {
        int o = i / 20, pp = i - o * 20;
        float4 ev = *(const float4*)(enc + o * 80 + pp * 4);   // e0x,e0y,e1x,e1y
        float2 dA = *(const float2*)(dec + o * 80 + pp * 2);
        float2 dB = *(const float2*)(dec + o * 80 + 40 + pp * 2);
        float2 bv = *(const float2*)(osc_bias + o * 40 + pp * 2);
        uint32_t ex2, ey2, dA2, dB2, b2;
        asm("cvt.rn.bf16x2.f32 %0, %1, %2;" : "=r"(ex2) : "f"(ev.z), "f"(ev.x));
        asm("cvt.rn.bf16x2.f32 %0, %1, %2;" : "=r"(ey2) : "f"(ev.w), "f"(ev.y));
        asm("cvt.rn.bf16x2.f32 %0, %1, %2;" : "=r"(dA2) : "f"(dA.y), "f"(dA.x));
        asm("cvt.rn.bf16x2.f32 %0, %1, %2;" : "=r"(dB2) : "f"(dB.y), "f"(dB.x));
        asm("cvt.rn.bf16x2.f32 %0, %1, %2;" : "=r"(b2)  : "f"(bv.y), "f"(bv.x));
        s_ed4[i] = make_uint4(ex2, ey2, dA2, dB2);
        s_bs[i] = b2;
    }
    for (int i = tid; i < NOSC * BT; i += NTHR) {
        int o = i >> 5, b = i & 31;
        s_os[o * 32 + b] = ((const float2*)g_os)[o * BATCH + b0 + b];
    }

    // ---- MMA warp role: (mt, kslice) ----
    const int mt = wrp >> 3;
    const int sk = wrp & 7;
    const int h0b = sk ? 8 * sk + 1 : 0;
    const int h0n = sk ? 8 : 9;
    const int h1b = (sk < 4) ? 65 + 8 * sk : 69 + 7 * sk;
    const int h1n = (sk < 4) ? 8 : 7;

    // ---- epilogue role (warps 8..15): emt, ent ----
    const int emt = (wrp >> 2) & 1;
    const int ent = wrp & 3;
    const int j0 = ent * 8 + ((lane & 3) << 1);
    const float b4j0  = fc4_b[j0],      b4j1  = fc4_b[j0 + 1];
    const float w50j0 = fc5_w[j0],      w50j1 = fc5_w[j0 + 1];
    const float w51j0 = fc5_w[32 + j0], w51j1 = fc5_w[32 + j0 + 1];

    // ---- fused store pointers (conflict-free swizzle) ----
    const int tbb7  = lane & 7;
    const int tregm = (lane >> 3) & 1;
    const int tmt   = lane >> 4;
    const int mxv   = ((tbb7 >> 1) & 3) << 2;
    char* paBase = smem + SM_AF + 4 * ((tbb7 << 4) + tregm) + tmt * 512;
    char* pa0 = paBase + 4 * (0  ^ mxv);
    char* pa1 = paBase + 4 * (4  ^ mxv);
    char* pa2 = paBase + 4 * (8  ^ mxv);
    char* pa3 = paBase + 4 * (12 ^ mxv);
    const int F0 = tmt * 8;        // rh=0 -> bit1 = tmt
    const int F1 = 8 - tmt * 8;    // rh=1 -> bit1 = 1^tmt

    // ---- MMA read pointers ----
    const char* afB = smem + SM_AF + mt * 512
                    + 4 * ((lane * 4) ^ (((lane >> 3) & 3) << 2));
    const char* wfB = (const char*)g_wfrag + lane * 32;

    // ---- limb state on warp 15 ----
    float th = 0.f, om = 0.f, l1s = 0.f, l2s = 0.f, dir0 = 0.f, dir1 = 0.f;
    float fc5b0 = 0.f, fc5b1 = 0.f;
    if (wrp == 15) {
        int b = b0 + lane;
        th  = x[b * 2];
        om  = 0.f;
        l1s = L0C - RC * th;
        l2s = L0C + RC * th;
        dir0 = g_direct[b * 2 + 0];
        dir1 = g_direct[b * 2 + 1];
        fc5b0 = fc5_b[0];
        fc5b1 = fc5_b[1];
    }

    __syncthreads();

    // ---- prologue: A(0) H0 (osc 0..25) ----
    FUSED_PHASE(0, 832);
    __syncthreads();

    float4 acc0 = make_float4(0.f, 0.f, 0.f, 0.f);
    float4 acc1 = make_float4(0.f, 0.f, 0.f, 0.f);
    float4 acc2 = make_float4(0.f, 0.f, 0.f, 0.f);
    float4 acc3 = make_float4(0.f, 0.f, 0.f, 0.f);

    for (int t = 0; t < STEPS; t++) {
        // ===== Region A(t): epi C(t-1) | fused H1(t) | MMA H0(t) =====
        if (t > 0 && wrp >= 8) { EPILOGUE_COMBINE() }
        FUSED_PHASE(26, 768);
        MMA_SEG(h0b, h0n)
        __syncthreads();

        // ===== Region B(t): limb(t-1) | fused H0(t+1) | MMA H1(t) | C-store =====
        if (t > 0 && wrp == 15) { LIMB_STEP(t - 1) }
        if (t < STEPS - 1) { FUSED_PHASE(0, 832) }
        MMA_SEG(h1b, h1n)
        {
            float4* cp = (float4*)(smem + SM_CP) + ((mt * 8 + sk) * 4) * 32 + lane;
            cp[0]  = acc0;  cp[32] = acc1;  cp[64] = acc2;  cp[96] = acc3;
            acc0 = make_float4(0.f, 0.f, 0.f, 0.f);
            acc1 = make_float4(0.f, 0.f, 0.f, 0.f);
            acc2 = make_float4(0.f, 0.f, 0.f, 0.f);
            acc3 = make_float4(0.f, 0.f, 0.f, 0.f);
        }
        __syncthreads();
    }

    // ===== drain: epilogue + limb for step STEPS-1 =====
    if (wrp >= 8) { EPILOGUE_COMBINE() }
    __syncthreads();
    if (wrp == 15) { LIMB_STEP(STEPS - 1) }
}

// ============================================================
// Launch
// ============================================================
extern "C" void kernel_launch(void* const* d_in, const int* in_sizes, int n_in,
                              void* d_out, int out_size)
{
    const float* x      = (const float*)d_in[0];
    const float* fc1_w  = (const float*)d_in[1];
    const float* fc1_b  = (const float*)d_in[2];
    const float* fc2_w  = (const float*)d_in[3];
    const float* fc2_b  = (const float*)d_in[4];
    const float* fc3_w  = (const float*)d_in[5];
    const float* fc3_b  = (const float*)d_in[6];
    const float* fcd_w  = (const float*)d_in[7];
    const float* fcd_b  = (const float*)d_in[8];
    const float* enc    = (const float*)d_in[9];
    const float* oscb   = (const float*)d_in[10];
    const float* dec    = (const float*)d_in[11];
    const float* fc4_w  = (const float*)d_in[12];
    const float* fc4_b  = (const float*)d_in[13];
    const float* fc5_w  = (const float*)d_in[14];
    const float* fc5_b  = (const float*)d_in[15];

    float* out   = (float*)d_out;
    float* out_l = out;
    float* out_a = out + (size_t)STEPS * BATCH * 4;

    cudaFuncSetAttribute(sim_kernel, cudaFuncAttributeMaxDynamicSharedMemorySize, SMEM_BYTES);

    pre_kernel<<<BATCH, 128>>>(x, fc1_w, fc1_b, fc2_w, fc2_b, fc3_w, fc3_b, fcd_w, fcd_b);
    wf_kernel<<<(WF_U32 + 255) / 256, 256>>>(fc4_w);
    sim_kernel<<<NCTA, NTHR, SMEM_BYTES>>>(x, enc, oscb, dec, fc4_b, fc5_w, fc5_b, out_l, out_a);
}

// round 12
// speedup vs baseline: 9.9796x; 1.3508x over previous
#include <cuda_runtime.h>
#include <cuda_bf16.h>
#include <cuda_fp16.h>
#include <cstdint>

// ---------------- problem constants ----------------
#define BATCH   4096
#define NOSC    50
#define NPER    40
#define STEPS   700
#define BT      32
#define NCTA    (BATCH/BT)   // 128
#define NTHR    512

#define DTC     0.001f
#define RC      0.02f
#define L0C     0.1f
#define INERT   0.001f
#define DAMPC   0.01f
#define KMUS    50.0f
#define LREST   0.05f
#define TAUM    0.05f
#define HPI     1.5707963267948966f

#define NKS     63                 // ceil(2000/32) k-steps (K padded to 2016)
// W fp8 fragment store: [ks(63)][nt(4)][lane(32)][reg(2)] u32 (e4m3 x4)
#define WF_U32  (NKS*4*32*2)       // 16128

// ---------------- device scratch ----------------
__device__ float    g_os[NOSC * BATCH * 2];
__device__ float    g_direct[BATCH * 2];
__device__ uint32_t g_wfrag[WF_U32];

// ---------------- shared memory layout (bytes, 16B aligned) ----------------
// A-frag fp8: [ks(63)][mt(2)][512B chunk]; word = (tb&7)<<4 | ((c<<2)^mx) | ((rh^tmt)<<1) | rm
#define SM_AF    0         // 64512
#define SM_WF    64512     // 64512 : B fp8 [ks][nt][lane] uint2
#define SM_ED    129024    // 16000 : per (o,pp): uint4 = (ex2,ey2,dA2,dB2) f16x2
#define SM_BS    145024    // 4000  : per (o,pp): f16x2 bias
#define SM_OS    149024    // 12800 : osc states float2 [o*32+b] (fp32)
#define SM_CP    161824    // 32768 : C partials [(mt*8+sk)*4+nt][lane] float4
#define SM_PART  194592    // 1024  : fc5 partials
#define SMEM_BYTES 195616

// ============================================================
// Preamble: per-batch MLP -> direct, o0 (g_os), g_direct
// ============================================================
__global__ void pre_kernel(const float* __restrict__ x,
                           const float* __restrict__ fc1_w, const float* __restrict__ fc1_b,
                           const float* __restrict__ fc2_w, const float* __restrict__ fc2_b,
                           const float* __restrict__ fc3_w, const float* __restrict__ fc3_b,
                           const float* __restrict__ fcd_w, const float* __restrict__ fcd_b)
{
    __shared__ float sh[128];
    __shared__ float sh2[128];
    int t = threadIdx.x;
    int b = blockIdx.x;
    float x0 = x[b * 2 + 0];
    float x1 = x[b * 2 + 1];

    float h = fmaf(fc1_w[t * 2 + 0], x0, fmaf(fc1_w[t * 2 + 1], x1, fc1_b[t]));
    h = fmaxf(h, 0.0f);
    sh[t] = h;
    __syncthreads();

    const float4* h4 = (const float4*)sh;

    {
        float acc = fc2_b[t];
        const float4* w4 = (const float4*)&fc2_w[t * 128];
        #pragma unroll 8
        for (int i = 0; i < 32; i++) {
            float4 w = w4[i], hh = h4[i];
            acc = fmaf(w.x, hh.x, acc);
            acc = fmaf(w.y, hh.y, acc);
            acc = fmaf(w.z, hh.z, acc);
            acc = fmaf(w.w, hh.w, acc);
        }
        sh2[t] = fmaxf(acc, 0.0f);
    }

    if (t < 2) {
        float acc = fcd_b[t];
        const float4* w4 = (const float4*)&fcd_w[t * 128];
        #pragma unroll 8
        for (int i = 0; i < 32; i++) {
            float4 w = w4[i], hh = h4[i];
            acc = fmaf(w.x, hh.x, acc);
            acc = fmaf(w.y, hh.y, acc);
            acc = fmaf(w.z, hh.z, acc);
            acc = fmaf(w.w, hh.w, acc);
        }
        g_direct[b * 2 + t] = acc;
    }
    __syncthreads();

    if (t < 100) {
        float acc = fc3_b[t];
        const float4* w4 = (const float4*)&fc3_w[t * 128];
        const float4* g4 = (const float4*)sh2;
        #pragma unroll 8
        for (int i = 0; i < 32; i++) {
            float4 w = w4[i], hh = g4[i];
            acc = fmaf(w.x, hh.x, acc);
            acc = fmaf(w.y, hh.y, acc);
            acc = fmaf(w.z, hh.z, acc);
            acc = fmaf(w.w, hh.w, acc);
        }
        int o = t >> 1, d = t & 1;
        g_os[(o * BATCH + b) * 2 + d] = acc;
    }
}

// ============================================================
// Build fc4_w fp8 B-fragments, layout [ks][nt][lane][reg] (m16n8k32 e4m3)
// b_r: k = ks*32 + (lane&3)*4 + r*16 + {0..3}, n = lane>>2, j = nt*8 + n
// ============================================================
__global__ void wf_kernel(const float* __restrict__ fc4_w)
{
    int idx = blockIdx.x * 256 + threadIdx.x;
    if (idx >= WF_U32) return;
    int r    = idx & 1;
    int lane = (idx >> 1) & 31;
    int nt   = (idx >> 6) & 3;
    int ks   = idx >> 8;
    int k0 = ks * 32 + (lane & 3) * 4 + r * 16;
    int j  = nt * 8 + (lane >> 2);
    float v0 = (k0     < 2000) ? fc4_w[j * 2000 + k0]     : 0.0f;
    float v1 = (k0 + 1 < 2000) ? fc4_w[j * 2000 + k0 + 1] : 0.0f;
    float v2 = (k0 + 2 < 2000) ? fc4_w[j * 2000 + k0 + 2] : 0.0f;
    float v3 = (k0 + 3 < 2000) ? fc4_w[j * 2000 + k0 + 3] : 0.0f;
    unsigned short lo, hi;
    asm("cvt.rn.satfinite.e4m3x2.f32 %0, %1, %2;" : "=h"(lo) : "f"(v1), "f"(v0));
    asm("cvt.rn.satfinite.e4m3x2.f32 %0, %1, %2;" : "=h"(hi) : "f"(v3), "f"(v2));
    uint32_t pk;
    asm("mov.b32 %0, {%1, %2};" : "=r"(pk) : "h"(lo), "h"(hi));
    // store to [ks][nt][lane][r]
    g_wfrag[((ks * 4 + nt) * 32 + lane) * 2 + r] = pk;
}

// ============================================================
// helpers
// ============================================================
__device__ __forceinline__ __half2 u2h(uint32_t u) { return *reinterpret_cast<__half2*>(&u); }
__device__ __forceinline__ uint32_t h2u(__half2 h) { return *reinterpret_cast<uint32_t*>(&h); }

// ============================================================
// Main persistent simulation kernel: 128 CTAs x 512 thr
// Half split at osc 24 (= ks 30):
//  Region A(t): fused writes H1 (osc 24-49, ks 30-62); MMA reads H0 (ks 0-29)
//  Region B(t): fused writes H0(t+1) (osc 0-23);       MMA reads H1 (ks 30-62)
// ============================================================
#define MMA8(C, A0,A1,A2,A3, Bx,By)                                            \
    asm volatile(                                                              \
        "mma.sync.aligned.m16n8k32.row.col.f32.e4m3.e4m3.f32 "                 \
        "{%0,%1,%2,%3}, {%4,%5,%6,%7}, {%8,%9}, {%0,%1,%2,%3};\n"              \
        : "+f"(C.x), "+f"(C.y), "+f"(C.z), "+f"(C.w)                           \
        : "r"(A0), "r"(A1), "r"(A2), "r"(A3), "r"(Bx), "r"(By))

#define MMA_LOOP(KSB, KSN, FA,FB,FC,FD) {                                      \
    const char* ab = afB + (KSB) * 1024;                                       \
    const char* bb = wfB + (KSB) * 1024;                                       \
    _Pragma("unroll 5")                                                        \
    for (int i = 0; i < (KSN); i++) {                                          \
        uint4 Af  = *(const uint4*)(ab + i * 1024);                            \
        uint2 B0v = *(const uint2*)(bb + i * 1024);                            \
        uint2 B1v = *(const uint2*)(bb + i * 1024 + 256);                      \
        uint2 B2v = *(const uint2*)(bb + i * 1024 + 512);                      \
        uint2 B3v = *(const uint2*)(bb + i * 1024 + 768);                      \
        MMA8(acc0, Af.FA, Af.FB, Af.FC, Af.FD, B0v.x, B0v.y);                  \
        MMA8(acc1, Af.FA, Af.FB, Af.FC, Af.FD, B1v.x, B1v.y);                  \
        MMA8(acc2, Af.FA, Af.FB, Af.FC, Af.FD, B2v.x, B2v.y);                  \
        MMA8(acc3, Af.FA, Af.FB, Af.FC, Af.FD, B3v.x, B3v.y);                  \
    } }

#define MMA_SEG(KSB, KSN)                                                      \
    if (mt == 0) { MMA_LOOP(KSB, KSN, x, y, z, w) }                            \
    else         { MMA_LOOP(KSB, KSN, z, w, x, y) }

// one group = 4 activations (pp entries 2*IA, 2*IA+1) -> one fp8x4 store
#define GRP(IA, BVA, BVB, QC, RH, DD) {                                        \
    uint4 ea = edp[2*(IA)];                                                    \
    uint4 eb = edp[2*(IA)+1];                                                  \
    __half2 va = __hfma2(u2h(ea.x), osx2, __hfma2(u2h(ea.y), osy2, u2h(BVA))); \
    __half2 aa = __hmax2(va, z2);                                              \
    s0p = __hfma2(u2h(ea.z), aa, s0p);                                         \
    s1p = __hfma2(u2h(ea.w), aa, s1p);                                         \
    __half2 vb = __hfma2(u2h(eb.x), osx2, __hfma2(u2h(eb.y), osy2, u2h(BVB))); \
    __half2 ab_ = __hmax2(vb, z2);                                             \
    s0q = __hfma2(u2h(eb.z), ab_, s0q);                                        \
    s1q = __hfma2(u2h(eb.w), ab_, s1q);                                        \
    unsigned short lo_, hi_;                                                   \
    asm("cvt.rn.satfinite.e4m3x2.f16x2 %0, %1;" : "=h"(lo_) : "r"(h2u(aa)));   \
    asm("cvt.rn.satfinite.e4m3x2.f16x2 %0, %1;" : "=h"(hi_) : "r"(h2u(ab_)));  \
    uint32_t out_;                                                             \
    asm("mov.b32 %0, {%1, %2};" : "=r"(out_) : "h"(lo_), "h"(hi_));            \
    *(uint32_t*)((QC) + (DD)*1024 + ((RH) ? F1 : F0)) = out_;                  \
}

#define FUSED_PHASE(OBASE, NTASK)                                              \
for (int task = tid; task < (NTASK); task += NTHR) {                           \
    const int o = (OBASE) + (task >> 5);                                       \
    float2 osv = s_os[o * 32 + lane];                                          \
    const __half2 osx2 = __floats2half2_rn(osv.x, osv.x);                      \
    const __half2 osy2 = __floats2half2_rn(osv.y, osv.y);                      \
    const __half2 z2 = __floats2half2_rn(0.f, 0.f);                            \
    const uint4* edp = s_ed4 + o * 20;                                         \
    const uint4* bsp = (const uint4*)(s_bs + o * 20);                          \
    uint4 BQ0 = bsp[0], BQ1 = bsp[1], BQ2 = bsp[2], BQ3 = bsp[3], BQ4 = bsp[4];\
    __half2 s0p = z2, s0q = z2, s1p = z2, s1q = z2;                            \
    const int ksoff = ((o * 5) >> 2) * 1024;                                   \
    char* q0 = pa0 + ksoff;                                                    \
    char* q1 = pa1 + ksoff;                                                    \
    char* q2 = pa2 + ksoff;                                                    \
    char* q3 = pa3 + ksoff;                                                    \
    const int om = o & 3;                                                      \
    if (om == 0) {                                                             \
        GRP(0, BQ0.x, BQ0.y, q0, 0, 0) GRP(1, BQ0.z, BQ0.w, q1, 0, 0)          \
        GRP(2, BQ1.x, BQ1.y, q2, 0, 0) GRP(3, BQ1.z, BQ1.w, q3, 0, 0)          \
        GRP(4, BQ2.x, BQ2.y, q0, 1, 0) GRP(5, BQ2.z, BQ2.w, q1, 1, 0)          \
        GRP(6, BQ3.x, BQ3.y, q2, 1, 0) GRP(7, BQ3.z, BQ3.w, q3, 1, 0)          \
        GRP(8, BQ4.x, BQ4.y, q0, 0, 1) GRP(9, BQ4.z, BQ4.w, q1, 0, 1)          \
    } else if (om == 1) {                                                      \
        GRP(0, BQ0.x, BQ0.y, q2, 0, 0) GRP(1, BQ0.z, BQ0.w, q3, 0, 0)          \
        GRP(2, BQ1.x, BQ1.y, q0, 1, 0) GRP(3, BQ1.z, BQ1.w, q1, 1, 0)          \
        GRP(4, BQ2.x, BQ2.y, q2, 1, 0) GRP(5, BQ2.z, BQ2.w, q3, 1, 0)          \
        GRP(6, BQ3.x, BQ3.y, q0, 0, 1) GRP(7, BQ3.z, BQ3.w, q1, 0, 1)          \
        GRP(8, BQ4.x, BQ4.y, q2, 0, 1) GRP(9, BQ4.z, BQ4.w, q3, 0, 1)          \
    } else if (om == 2) {                                                      \
        GRP(0, BQ0.x, BQ0.y, q0, 1, 0) GRP(1, BQ0.z, BQ0.w, q1, 1, 0)          \
        GRP(2, BQ1.x, BQ1.y, q2, 1, 0) GRP(3, BQ1.z, BQ1.w, q3, 1, 0)          \
        GRP(4, BQ2.x, BQ2.y, q0, 0, 1) GRP(5, BQ2.z, BQ2.w, q1, 0, 1)          \
        GRP(6, BQ3.x, BQ3.y, q2, 0, 1) GRP(7, BQ3.z, BQ3.w, q3, 0, 1)          \
        GRP(8, BQ4.x, BQ4.y, q0, 1, 1) GRP(9, BQ4.z, BQ4.w, q1, 1, 1)          \
    } else {                                                                   \
        GRP(0, BQ0.x, BQ0.y, q2, 1, 0) GRP(1, BQ0.z, BQ0.w, q3, 1, 0)          \
        GRP(2, BQ1.x, BQ1.y, q0, 0, 1) GRP(3, BQ1.z, BQ1.w, q1, 0, 1)          \
        GRP(4, BQ2.x, BQ2.y, q2, 0, 1) GRP(5, BQ2.z, BQ2.w, q3, 0, 1)          \
        GRP(6, BQ3.x, BQ3.y, q0, 1, 1) GRP(7, BQ3.z, BQ3.w, q1, 1, 1)          \
        GRP(8, BQ4.x, BQ4.y, q2, 1, 1) GRP(9, BQ4.z, BQ4.w, q3, 1, 1)          \
    }                                                                          \
    __half2 hs0 = __hadd2(s0p, s0q);                                           \
    __half2 hs1 = __hadd2(s1p, s1q);                                           \
    float2 f0v = __half22float2(hs0);                                          \
    float2 f1v = __half22float2(hs1);                                          \
    float d0 = f0v.x + f0v.y;                                                  \
    float d1 = f1v.x + f1v.y;                                                  \
    s_os[o * 32 + lane] = make_float2(osv.x + DTC * d0, osv.y + DTC * d1);     \
}

#define EPILOGUE_COMBINE() {                                                   \
    const float4* cp = (const float4*)(smem + SM_CP) + (emt * 8 * 4 + ent) * 32 + lane; \
    float4 cs = cp[0];                                                         \
    _Pragma("unroll")                                                          \
    for (int s2 = 1; s2 < 8; s2++) {                                           \
        float4 v = cp[s2 * 128];                                               \
        cs.x += v.x; cs.y += v.y; cs.z += v.z; cs.w += v.w;                    \
    }                                                                          \
    float b00 = fmaxf(cs.x + b4j0, 0.f);                                       \
    float b01 = fmaxf(cs.y + b4j1, 0.f);                                       \
    float b10 = fmaxf(cs.z + b4j0, 0.f);                                       \
    float b11 = fmaxf(cs.w + b4j1, 0.f);                                       \
    float p00 = fmaf(w50j0, b00, w50j1 * b01);                                 \
    float p01 = fmaf(w51j0, b00, w51j1 * b01);                                 \
    float p10 = fmaf(w50j0, b10, w50j1 * b11);                                 \
    float p11 = fmaf(w51j0, b10, w51j1 * b11);                                 \
    _Pragma("unroll")                                                          \
    for (int off = 1; off <= 2; off <<= 1) {                                   \
        p00 += __shfl_xor_sync(0xffffffffu, p00, off);                         \
        p01 += __shfl_xor_sync(0xffffffffu, p01, off);                         \
        p10 += __shfl_xor_sync(0xffffffffu, p10, off);                         \
        p11 += __shfl_xor_sync(0xffffffffu, p11, off);                         \
    }                                                                          \
    if ((lane & 3) == 0) {                                                     \
        int m0 = emt * 16 + (lane >> 2);                                       \
        s_part[m0 * 8 + ent]           = p00;                                  \
        s_part[m0 * 8 + 4 + ent]       = p01;                                  \
        s_part[(m0 + 8) * 8 + ent]     = p10;                                  \
        s_part[(m0 + 8) * 8 + 4 + ent] = p11;                                  \
    }                                                                          \
}

#define LIMB_STEP(TOUT) {                                                      \
    float4 qq0 = *(const float4*)(s_part + lane * 8);                          \
    float4 qq1 = *(const float4*)(s_part + lane * 8 + 4);                      \
    float A0 = fc5b0 + dir0 + ((qq0.x + qq0.y) + (qq0.z + qq0.w));             \
    float A1 = fc5b1 + dir1 + ((qq1.x + qq1.y) + (qq1.z + qq1.w));             \
    float f1 = fmaxf(A0, 0.f) * KMUS * fmaxf(l1s - LREST, 0.f);                \
    float f2 = fmaxf(A1, 0.f) * KMUS * fmaxf(l2s - LREST, 0.f);                \
    float domega = (RC * (f2 - f1) - DAMPC * om) / INERT;                      \
    float dl1 = ((L0C - RC * th) - l1s) / TAUM;                                \
    float dl2 = ((L0C + RC * th) - l2s) / TAUM;                                \
    float pos = th + DTC * om;                                                 \
    float vel = om + DTC * domega;                                             \
    l1s += DTC * dl1;                                                          \
    l2s += DTC * dl2;                                                          \
    bool inb = (pos > -HPI) && (pos < HPI);                                    \
    th = fminf(fmaxf(pos, -HPI), HPI);                                         \
    om = inb ? vel : 0.f;                                                      \
    size_t lidx = (size_t)(TOUT) * BATCH + b0 + lane;                          \
    *(float4*)(out_l + lidx * 4)   = make_float4(th, om, l1s, l2s);            \
    *(float2*)(out_act + lidx * 2) = make_float2(A0, A1);                      \
}

extern "C" __global__ void __launch_bounds__(NTHR, 1)
sim_kernel(const float* __restrict__ x,
           const float* __restrict__ enc,
           const float* __restrict__ osc_bias,
           const float* __restrict__ dec,
           const float* __restrict__ fc4_b,
           const float* __restrict__ fc5_w,
           const float* __restrict__ fc5_b,
           float* __restrict__ out_l,
           float* __restrict__ out_act)
{
    extern __shared__ char smem[];
    uint4*    s_ed4  = (uint4*)   (smem + SM_ED);
    uint32_t* s_bs   = (uint32_t*)(smem + SM_BS);
    float2*   s_os   = (float2*)  (smem + SM_OS);
    float*    s_part = (float*)   (smem + SM_PART);

    const int tid  = threadIdx.x;
    const int lane = tid & 31;
    const int wrp  = tid >> 5;
    const int b0   = blockIdx.x * BT;

    // ---- zero A-frag buffer (pad slots must be finite; stays 0 in pad) ----
    for (int i = tid; i < 16128; i += NTHR) ((uint32_t*)(smem + SM_AF))[i] = 0u;
    // ---- copy fp8 W fragments into SMEM ----
    {
        const uint4* src = (const uint4*)g_wfrag;
        uint4* dst = (uint4*)(smem + SM_WF);
        for (int i = tid; i < WF_U32 / 4; i += NTHR) dst[i] = src[i];
    }
    // ---- packed f16 enc/dec/bias tables ----
    for (int i = tid; i < 1000; i += NTHR) {
        int o = i / 20, pp = i - o * 20;
        float4 ev = *(const float4*)(enc + o * 80 + pp * 4);
        float2 dA = *(const float2*)(dec + o * 80 + pp * 2);
        float2 dB = *(const float2*)(dec + o * 80 + 40 + pp * 2);
        float2 bv = *(const float2*)(osc_bias + o * 40 + pp * 2);
        __half2 ex2 = __floats2half2_rn(ev.x, ev.z);
        __half2 ey2 = __floats2half2_rn(ev.y, ev.w);
        __half2 dA2 = __floats2half2_rn(dA.x, dA.y);
        __half2 dB2 = __floats2half2_rn(dB.x, dB.y);
        __half2 b2  = __floats2half2_rn(bv.x, bv.y);
        s_ed4[i] = make_uint4(h2u(ex2), h2u(ey2), h2u(dA2), h2u(dB2));
        s_bs[i] = h2u(b2);
    }
    for (int i = tid; i < NOSC * BT; i += NTHR) {
        int o = i >> 5, b = i & 31;
        s_os[o * 32 + b] = ((const float2*)g_os)[o * BATCH + b0 + b];
    }

    // ---- MMA warp role: (mt, kslice) ----
    const int mt = wrp >> 3;
    const int sk = wrp & 7;
    const int h0b = (sk < 6) ? 4 * sk : 24 + 3 * (sk - 6);   // H0: ks 0..29
    const int h0n = (sk < 6) ? 4 : 3;
    const int h1b = (sk == 0) ? 30 : 31 + 4 * sk;            // H1: ks 30..62
    const int h1n = (sk == 0) ? 5 : 4;

    // ---- epilogue role (warps 8..15) ----
    const int emt = (wrp >> 2) & 1;
    const int ent = wrp & 3;
    const int j0 = ent * 8 + ((lane & 3) << 1);
    const float b4j0  = fc4_b[j0],      b4j1  = fc4_b[j0 + 1];
    const float w50j0 = fc5_w[j0],      w50j1 = fc5_w[j0 + 1];
    const float w51j0 = fc5_w[32 + j0], w51j1 = fc5_w[32 + j0 + 1];

    // ---- fused store pointers (conflict-free swizzle; tb = lane) ----
    const int tbb7  = lane & 7;
    const int tregm = (lane >> 3) & 1;
    const int tmt   = lane >> 4;
    const int mxv   = ((tbb7 >> 1) & 3) << 2;
    char* paBase = smem + SM_AF + 4 * ((tbb7 << 4) + tregm) + tmt * 512;
    char* pa0 = paBase + 4 * (0  ^ mxv);
    char* pa1 = paBase + 4 * (4  ^ mxv);
    char* pa2 = paBase + 4 * (8  ^ mxv);
    char* pa3 = paBase + 4 * (12 ^ mxv);
    const int F0 = tmt * 8;        // rh=0 -> word bit1 = tmt
    const int F1 = 8 - tmt * 8;    // rh=1 -> word bit1 = 1^tmt

    // ---- MMA read pointers ----
    const char* afB = smem + SM_AF + mt * 512
                    + 4 * ((lane * 4) ^ (((lane >> 3) & 3) << 2));
    const char* wfB = smem + SM_WF + lane * 8;

    // ---- limb state on warp 15 ----
    float th = 0.f, om = 0.f, l1s = 0.f, l2s = 0.f, dir0 = 0.f, dir1 = 0.f;
    float fc5b0 = 0.f, fc5b1 = 0.f;
    if (wrp == 15) {
        int b = b0 + lane;
        th  = x[b * 2];
        om  = 0.f;
        l1s = L0C - RC * th;
        l2s = L0C + RC * th;
        dir0 = g_direct[b * 2 + 0];
        dir1 = g_direct[b * 2 + 1];
        fc5b0 = fc5_b[0];
        fc5b1 = fc5_b[1];
    }

    __syncthreads();

    // ---- prologue: A(0) H0 (osc 0..23) ----
    FUSED_PHASE(0, 768);
    __syncthreads();

    float4 acc0 = make_float4(0.f, 0.f, 0.f, 0.f);
    float4 acc1 = make_float4(0.f, 0.f, 0.f, 0.f);
    float4 acc2 = make_float4(0.f, 0.f, 0.f, 0.f);
    float4 acc3 = make_float4(0.f, 0.f, 0.f, 0.f);

    for (int t = 0; t < STEPS; t++) {
        // ===== Region A(t): epi C(t-1) | fused H1(t) | MMA H0(t) =====
        if (t > 0 && wrp >= 8) { EPILOGUE_COMBINE() }
        FUSED_PHASE(24, 832);
        MMA_SEG(h0b, h0n)
        __syncthreads();

        // ===== Region B(t): limb(t-1) | fused H0(t+1) | MMA H1(t) | C-store =====
        if (t > 0 && wrp == 15) { LIMB_STEP(t - 1) }
        if (t < STEPS - 1) { FUSED_PHASE(0, 768) }
        MMA_SEG(h1b, h1n)
        {
            float4* cp = (float4*)(smem + SM_CP) + ((mt * 8 + sk) * 4) * 32 + lane;
            cp[0]  = acc0;  cp[32] = acc1;  cp[64] = acc2;  cp[96] = acc3;
            acc0 = make_float4(0.f, 0.f, 0.f, 0.f);
            acc1 = make_float4(0.f, 0.f, 0.f, 0.f);
            acc2 = make_float4(0.f, 0.f, 0.f, 0.f);
            acc3 = make_float4(0.f, 0.f, 0.f, 0.f);
        }
        __syncthreads();
    }

    // ===== drain: epilogue + limb for step STEPS-1 =====
    if (wrp >= 8) { EPILOGUE_COMBINE() }
    __syncthreads();
    if (wrp == 15) { LIMB_STEP(STEPS - 1) }
}

// ============================================================
// Launch
// ============================================================
extern "C" void kernel_launch(void* const* d_in, const int* in_sizes, int n_in,
                              void* d_out, int out_size)
{
    const float* x      = (const float*)d_in[0];
    const float* fc1_w  = (const float*)d_in[1];
    const float* fc1_b  = (const float*)d_in[2];
    const float* fc2_w  = (const float*)d_in[3];
    const float* fc2_b  = (const float*)d_in[4];
    const float* fc3_w  = (const float*)d_in[5];
    const float* fc3_b  = (const float*)d_in[6];
    const float* fcd_w  = (const float*)d_in[7];
    const float* fcd_b  = (const float*)d_in[8];
    const float* enc    = (const float*)d_in[9];
    const float* oscb   = (const float*)d_in[10];
    const float* dec    = (const float*)d_in[11];
    const float* fc4_w  = (const float*)d_in[12];
    const float* fc4_b  = (const float*)d_in[13];
    const float* fc5_w  = (const float*)d_in[14];
    const float* fc5_b  = (const float*)d_in[15];

    float* out   = (float*)d_out;
    float* out_l = out;
    float* out_a = out + (size_t)STEPS * BATCH * 4;

    cudaFuncSetAttribute(sim_kernel, cudaFuncAttributeMaxDynamicSharedMemorySize, SMEM_BYTES);

    pre_kernel<<<BATCH, 128>>>(x, fc1_w, fc1_b, fc2_w, fc2_b, fc3_w, fc3_b, fcd_w, fcd_b);
    wf_kernel<<<(WF_U32 + 255) / 256, 256>>>(fc4_w);
    sim_kernel<<<NCTA, NTHR, SMEM_BYTES>>>(x, enc, oscb, dec, fc4_b, fc5_w, fc5_b, out_l, out_a);
}